// round 12
// baseline (speedup 1.0000x reference)
#include <cuda_runtime.h>
#include <cuda_fp16.h>
#include <math.h>
#include <stdint.h>

#define Bb   4
#define Tt   2048
#define Dd   1024
#define Hh   4
#define DKk  256
#define DVv  512
#define KDIM 1024
#define VDIM 2048
#define FFND 4096
#define NROWS (Bb*Tt)   /* 8192 */
#define NQKVG 6144

// ---------------- scratch ----------------
__device__ __half  g_normh[NROWS*Dd];
__device__ __half  g_xallh[(size_t)NROWS*NQKVG];
__device__ float   g_q[NROWS*KDIM];
__device__ float   g_k[NROWS*KDIM];
__device__ float   g_v[NROWS*VDIM];
__device__ float   g_gg[NROWS*Hh];
__device__ float   g_bb[NROWS*Hh];
__device__ float   g_o[NROWS*VDIM];
__device__ __half  g_oh[NROWS*VDIM];
__device__ float   g_x2[NROWS*Dd];
__device__ __half  g_hbufh[NROWS*Dd];
__device__ __half  g_ffn1h[(size_t)NROWS*FFND];
__device__ __half  g_wth[16*1024*1024];
#define WT_QKVG 0
#define WT_O   (6*1024*1024)
#define WT_F1  (8*1024*1024)
#define WT_F2  (12*1024*1024)

// ---------------- helpers ----------------
__device__ __forceinline__ float sigmoidf_(float x) { return 1.0f / (1.0f + expf(-x)); }
__device__ __forceinline__ float siluf_(float x)    { return x * sigmoidf_(x); }
__device__ __forceinline__ float geluf_(float x)    { return 0.5f * x * (1.0f + erff(x * 0.70710678118654752f)); }
__device__ __forceinline__ float softplusf_(float x){ return (x > 20.0f) ? x : log1pf(expf(x)); }
__device__ __forceinline__ uint32_t smem_u32(const void* p) {
    uint32_t a;
    asm("{ .reg .u64 t; cvta.to.shared.u64 t, %1; cvt.u32.u64 %0, t; }" : "=r"(a) : "l"(p));
    return a;
}
__device__ __forceinline__ void cpa16(uint32_t dst, const void* src) {
    asm volatile("cp.async.cg.shared.global [%0], [%1], 16;" :: "r"(dst), "l"(src));
}
__device__ __forceinline__ void cpa4(uint32_t dst, const void* src) {
    asm volatile("cp.async.ca.shared.global [%0], [%1], 4;" :: "r"(dst), "l"(src));
}
__device__ __forceinline__ void ldm4(uint32_t* r, uint32_t addr) {
    asm volatile("ldmatrix.sync.aligned.m8n8.x4.shared.b16 {%0,%1,%2,%3}, [%4];"
        : "=r"(r[0]), "=r"(r[1]), "=r"(r[2]), "=r"(r[3]) : "r"(addr));
}
#define SWZ(o) ((o) ^ (((o) >> 3) & 0x70))

typedef unsigned long long u64t;
#define FMA2(d, a, b, c) asm("fma.rn.f32x2 %0, %1, %2, %3;" : "=l"(d) : "l"(a), "l"(b), "l"(c))
#define MUL2(d, a, b)    asm("mul.rn.f32x2 %0, %1, %2;"     : "=l"(d) : "l"(a), "l"(b))
#define ADD2(d, a, b)    asm("add.rn.f32x2 %0, %1, %2;"     : "=l"(d) : "l"(a), "l"(b))
#define PACK2(d, lo, hi) asm("mov.b64 %0, {%1, %2};" : "=l"(d) : "f"(lo), "f"(hi))
#define UNPK2(lo, hi, s) asm("mov.b64 {%0, %1}, %2;" : "=f"(lo), "=f"(hi) : "l"(s))

// ---------------- ONE fused transpose launch: 7 matrices, src[K,N] -> half dst[N,K] ----------------
__global__ void transpose_all_kernel(const float* __restrict__ Wq, const float* __restrict__ Wk,
                                     const float* __restrict__ Wv, const float* __restrict__ Wg,
                                     const float* __restrict__ Wo, const float* __restrict__ F1,
                                     const float* __restrict__ F2, __half* __restrict__ wth) {
    const int cum[7] = {1024, 2048, 4096, 6144, 8192, 12288, 16384};
    const int Ks[7]  = {1024, 1024, 1024, 1024, 2048, 1024, 4096};
    const int Ns[7]  = {1024, 1024, 2048, 2048, 1024, 4096, 1024};
    const size_t doff[7] = {0, 1024*1024, 2*1024*1024, 4*1024*1024,
                            6*1024*1024, 8*1024*1024, 12*1024*1024};
    int bid = blockIdx.x;
    int m = 0;
    #pragma unroll
    for (int i = 0; i < 7; i++) if (bid >= cum[i]) m = i + 1;
    int lt = bid - (m ? cum[m - 1] : 0);
    const float* srcs[7] = {Wq, Wk, Wv, Wg, Wo, F1, F2};
    const float* src = srcs[m];
    __half* dst = wth + doff[m];
    int K = Ks[m], N = Ns[m];
    int tilesN = N >> 5;
    int nb = (lt % tilesN) * 32, kb = (lt / tilesN) * 32;

    __shared__ float t[32][33];
    int x = threadIdx.x, y = threadIdx.y;
    #pragma unroll
    for (int i = 0; i < 4; i++)
        t[y + 8 * i][x] = src[(size_t)(kb + y + 8 * i) * N + nb + x];
    __syncthreads();
    #pragma unroll
    for (int i = 0; i < 4; i++)
        dst[(size_t)(nb + y + 8 * i) * K + kb + x] = __float2half(t[x][y + 8 * i]);
}

// ---------------- fp16 mma.sync GEMM 128x128, 2-stage cp.async, 2 CTAs/SM ----------------
// EPI: 2 half bias+gelu | 3 float +res | 4 float bias+res | 5 half none
#define STG_BYTES 32768
#define SMEM_DYN (2 * STG_BYTES)

template<int EPI>
__global__ void __launch_bounds__(256)
hgemm(const __half* __restrict__ A, const __half* __restrict__ Bt, void* __restrict__ Cv,
      int M_, int N_, int K_, const float* __restrict__ bias, const float* __restrict__ res) {
    extern __shared__ char sm[];
    uint32_t sbase = smem_u32(sm);
    int tid = threadIdx.x, wid = tid >> 5, lane = tid & 31;
    int g = lane >> 2, tg = lane & 3;
    int bm = blockIdx.y * 128, bn = blockIdx.x * 128;
    int wm = (wid & 1) * 64, wn = (wid >> 1) * 32;

    int lrow = tid >> 1, lc0 = (tid & 1) * 4;
    const __half* gA = A + (size_t)(bm + lrow) * K_ + lc0 * 8;
    const __half* gB = Bt + (size_t)(bn + lrow) * K_ + lc0 * 8;
    uint32_t sAo[4], sBo[4];
    #pragma unroll
    for (int i = 0; i < 4; i++) {
        uint32_t off = lrow * 128 + (lc0 + i) * 16;
        sAo[i] = SWZ(off);
        sBo[i] = 16384 + SWZ(off);
    }
    auto load_stage = [&](int chunk, int stage) {
        uint32_t st = sbase + stage * STG_BYTES;
        const __half* a = gA + chunk * 64;
        const __half* b = gB + chunk * 64;
        #pragma unroll
        for (int i = 0; i < 4; i++) cpa16(st + sAo[i], a + i * 8);
        #pragma unroll
        for (int i = 0; i < 4; i++) cpa16(st + sBo[i], b + i * 8);
        asm volatile("cp.async.commit_group;" ::: "memory");
    };

    int arow = lane & 15;
    int acb  = (lane >> 4) * 16;
    int bsel = lane >> 3;
    int brow = (lane & 7) + ((bsel & 2) ? 8 : 0);
    int bcb  = (bsel & 1) * 16;
    uint32_t aBase[4], bBase[2];
    #pragma unroll
    for (int mt = 0; mt < 4; mt++)
        aBase[mt] = (wm + mt * 16 + arow) * 128 + acb;
    #pragma unroll
    for (int np = 0; np < 2; np++)
        bBase[np] = 16384 + (wn + np * 16 + brow) * 128 + bcb;

    float acc[4][4][4];
    #pragma unroll
    for (int i = 0; i < 4; i++)
        #pragma unroll
        for (int j = 0; j < 4; j++)
            #pragma unroll
            for (int r = 0; r < 4; r++) acc[i][j][r] = 0.f;

    const int NK = K_ >> 6;
    load_stage(0, 0);
    load_stage(1, 1);

    for (int k = 0; k < NK; k++) {
        int sk = k & 1;
        asm volatile("cp.async.wait_group %0;" :: "n"(1) : "memory");
        __syncthreads();
        uint32_t st = sbase + sk * STG_BYTES;

        #pragma unroll
        for (int kk = 0; kk < 4; kk++) {
            int kbyte = kk * 32;
            uint32_t af[4][4], bf[4][2];
            #pragma unroll
            for (int mt = 0; mt < 4; mt++)
                ldm4(af[mt], st + SWZ(aBase[mt] + kbyte));
            #pragma unroll
            for (int np = 0; np < 2; np++) {
                uint32_t r4[4];
                ldm4(r4, st + SWZ(bBase[np] + kbyte));
                bf[2 * np][0] = r4[0]; bf[2 * np][1] = r4[1];
                bf[2 * np + 1][0] = r4[2]; bf[2 * np + 1][1] = r4[3];
            }
            #pragma unroll
            for (int mt = 0; mt < 4; mt++)
                #pragma unroll
                for (int nt = 0; nt < 4; nt++)
                    asm volatile(
                        "mma.sync.aligned.m16n8k16.row.col.f32.f16.f16.f32 "
                        "{%0,%1,%2,%3}, {%4,%5,%6,%7}, {%8,%9}, {%0,%1,%2,%3};"
                        : "+f"(acc[mt][nt][0]), "+f"(acc[mt][nt][1]),
                          "+f"(acc[mt][nt][2]), "+f"(acc[mt][nt][3])
                        : "r"(af[mt][0]), "r"(af[mt][1]), "r"(af[mt][2]), "r"(af[mt][3]),
                          "r"(bf[nt][0]), "r"(bf[nt][1]));
        }
        __syncthreads();
        if (k + 2 < NK) load_stage(k + 2, sk);
        else asm volatile("cp.async.commit_group;" ::: "memory");
    }

    float* Cf = (float*)Cv;
    __half* Ch = (__half*)Cv;
    #pragma unroll
    for (int mt = 0; mt < 4; mt++) {
        #pragma unroll
        for (int nt = 0; nt < 4; nt++) {
            int col = bn + wn + nt * 8 + 2 * tg;
            float b0 = 0.f, b1 = 0.f;
            if (EPI == 2 || EPI == 4) { b0 = bias[col]; b1 = bias[col + 1]; }
            #pragma unroll
            for (int h2 = 0; h2 < 2; h2++) {
                int row = bm + wm + mt * 16 + g + h2 * 8;
                float v0 = acc[mt][nt][2 * h2], v1 = acc[mt][nt][2 * h2 + 1];
                if (EPI == 2 || EPI == 4) { v0 += b0; v1 += b1; }
                if (EPI == 2 || EPI == 5) {
                    __half2 hv;
                    hv.x = __float2half(EPI == 2 ? geluf_(v0) : v0);
                    hv.y = __float2half(EPI == 2 ? geluf_(v1) : v1);
                    *(__half2*)(Ch + (size_t)row * N_ + col) = hv;
                } else {
                    if (EPI == 3 || EPI == 4) {
                        float2 rr = *(const float2*)(res + (size_t)row * N_ + col);
                        v0 += rr.x; v1 += rr.y;
                    }
                    float2 o2; o2.x = v0; o2.y = v1;
                    *(float2*)(Cf + (size_t)row * N_ + col) = o2;
                }
            }
        }
    }
}

// ---------------- LayerNorm -> half ----------------
__global__ void ln_kernel(const float* __restrict__ x, const float* __restrict__ w,
                          const float* __restrict__ b, __half* __restrict__ out) {
    int row = blockIdx.x;
    const float* xr = x + (size_t)row * Dd;
    float s1 = 0.f, s2 = 0.f;
    float vals[4];
    #pragma unroll
    for (int i = 0; i < 4; i++) {
        float v = xr[threadIdx.x + i * 256];
        vals[i] = v; s1 += v; s2 += v * v;
    }
    __shared__ float sh[2][8];
    int lane = threadIdx.x & 31, wid = threadIdx.x >> 5;
    #pragma unroll
    for (int off = 16; off > 0; off >>= 1) {
        s1 += __shfl_xor_sync(0xffffffffu, s1, off);
        s2 += __shfl_xor_sync(0xffffffffu, s2, off);
    }
    if (lane == 0) { sh[0][wid] = s1; sh[1][wid] = s2; }
    __syncthreads();
    if (threadIdx.x == 0) {
        float a = 0.f, c = 0.f;
        #pragma unroll
        for (int i = 0; i < 8; i++) { a += sh[0][i]; c += sh[1][i]; }
        sh[0][0] = a; sh[1][0] = c;
    }
    __syncthreads();
    float mean = sh[0][0] * (1.0f / Dd);
    float var  = sh[1][0] * (1.0f / Dd) - mean * mean;
    float inv  = rsqrtf(var + 1e-5f);
    #pragma unroll
    for (int i = 0; i < 4; i++) {
        int c = threadIdx.x + i * 256;
        out[(size_t)row * Dd + c] = __float2half((vals[i] - mean) * inv * w[c] + b[c]);
    }
}

// ---------------- g / beta ----------------
__global__ void gbeta_kernel(const __half* __restrict__ normed, const float* __restrict__ Wa,
                             const float* __restrict__ Wb, const float* __restrict__ A_log,
                             const float* __restrict__ dt_bias, float* __restrict__ g,
                             float* __restrict__ beta) {
    int row = blockIdx.x * 8 + (threadIdx.x >> 5);
    int lane = threadIdx.x & 31;
    const __half* xr = normed + (size_t)row * Dd;
    float acc[8];
    #pragma unroll
    for (int j = 0; j < 8; j++) acc[j] = 0.f;
    for (int k = lane; k < Dd; k += 32) {
        float xv = __half2float(xr[k]);
        const float* wa = Wa + k * 4;
        const float* wb = Wb + k * 4;
        #pragma unroll
        for (int j = 0; j < 4; j++) { acc[j] += xv * wa[j]; acc[4 + j] += xv * wb[j]; }
    }
    #pragma unroll
    for (int off = 16; off > 0; off >>= 1)
        #pragma unroll
        for (int j = 0; j < 8; j++) acc[j] += __shfl_xor_sync(0xffffffffu, acc[j], off);
    if (lane < 4) {
        float xa = acc[lane] + dt_bias[lane];
        g[row * 4 + lane] = -expf(A_log[lane]) * softplusf_(xa);
        beta[row * 4 + lane] = sigmoidf_(acc[4 + lane]);
    }
}

// ---------------- fused conv+SiLU+l2norm for q AND k (half2 vectorized) ----------------
__global__ void conv_l2_kernel(const __half* __restrict__ xall,
                               const float* __restrict__ wq, const float* __restrict__ wk,
                               float* __restrict__ qout, float* __restrict__ kout) {
    int bid = blockIdx.x;
    bool isq = bid < NROWS * Hh;
    int rowh = isq ? bid : bid - NROWS * Hh;
    long row = rowh >> 2;
    int h = rowh & 3;
    int t = (int)(row & (Tt - 1));
    long bbase = row - t;
    int c = h * DKk + threadIdx.x * 2;
    int coff = isq ? 0 : 1024;
    const float* w = isq ? wq : wk;
    float wA[2][4] = {{w[c*4+0], w[c*4+1], w[c*4+2], w[c*4+3]},
                      {w[c*4+4], w[c*4+5], w[c*4+6], w[c*4+7]}};
    float a0 = 0.f, a1 = 0.f;
    #pragma unroll
    for (int i = 0; i < 4; i++) {
        int tt = t - 3 + i;
        if (tt >= 0) {
            __half2 hv = *(const __half2*)(xall + (bbase + tt) * (long)NQKVG + coff + c);
            float2 fv = __half22float2(hv);
            a0 += fv.x * wA[0][i];
            a1 += fv.y * wA[1][i];
        }
    }
    float v0 = siluf_(a0), v1 = siluf_(a1);
    float ss = v0 * v0 + v1 * v1;
    __shared__ float sh[4];
    int lane = threadIdx.x & 31, wid = threadIdx.x >> 5;
    #pragma unroll
    for (int off = 16; off > 0; off >>= 1) ss += __shfl_xor_sync(0xffffffffu, ss, off);
    if (lane == 0) sh[wid] = ss;
    __syncthreads();
    if (threadIdx.x == 0) sh[0] = sh[0] + sh[1] + sh[2] + sh[3];
    __syncthreads();
    float sc = (isq ? 0.0625f : 1.0f) * rsqrtf(sh[0] + 1e-6f);
    float* outp = isq ? qout : kout;
    float2 o2; o2.x = v0 * sc; o2.y = v1 * sc;
    *(float2*)(outp + row * KDIM + c) = o2;
}

// ---------------- conv + SiLU for V (half2 vectorized) ----------------
__global__ void conv_silu_kernel(const __half* __restrict__ x, int coff,
                                 const float* __restrict__ w,
                                 float* __restrict__ y, long total2) {
    long idx = (long)blockIdx.x * blockDim.x + threadIdx.x;
    if (idx >= total2) return;
    int c = (int)(idx % (VDIM / 2)) * 2;
    long bt = idx / (VDIM / 2);
    int t = (int)(bt % Tt);
    long bbase = (bt / Tt) * Tt;
    const float* w4 = w + c * 4;
    float a0 = 0.f, a1 = 0.f;
    #pragma unroll
    for (int i = 0; i < 4; i++) {
        int tt = t - 3 + i;
        if (tt >= 0) {
            __half2 hv = *(const __half2*)(x + (bbase + tt) * (long)NQKVG + coff + c);
            float2 fv = __half22float2(hv);
            a0 += fv.x * w4[i];
            a1 += fv.y * w4[4 + i];
        }
    }
    float2 o2; o2.x = siluf_(a0); o2.y = siluf_(a1);
    *(float2*)(y + bt * VDIM + c) = o2;
}

// ---------------- gated delta rule scan: 512 threads (8-lane k-split), cp.async ring ----------------
#define KSTR2 36
#define RD 8
__global__ void __launch_bounds__(512)
scan_kernel(const float* __restrict__ q, const float* __restrict__ k, const float* __restrict__ v,
            const float* __restrict__ g, const float* __restrict__ beta, float* __restrict__ o) {
    int b  = blockIdx.x >> 5;
    int h  = (blockIdx.x >> 3) & 3;
    int sl = blockIdx.x & 7;
    int v0 = sl * 64;
    int tid = threadIdx.x;
    int kb = tid & 7, vi = tid >> 3;     // 8 lanes per v-column, 64 columns
    int kb36 = kb * KSTR2;

    __shared__ float qs[RD][8 * KSTR2], ks[RD][8 * KSTR2], vs[RD][64], sgb[RD][2];

    // loaders: tid<256 load q/k element tid (transposed [kb][j] layout);
    // tid in [256,320): v; tid 320/321: g/beta
    const float* qpl = q + (size_t)b * Tt * KDIM + h * DKk + tid;          // valid tid<256
    const float* kpl = k + (size_t)b * Tt * KDIM + h * DKk + tid;
    const float* vpl = v + (size_t)b * Tt * VDIM + h * DVv + v0 + (tid - 256);
    const float* gp  = g + (size_t)b * Tt * Hh + h;
    const float* bp  = beta + (size_t)b * Tt * Hh + h;

    int le = tid & 255;
    uint32_t qdst0 = smem_u32(&qs[0][(le & 7) * KSTR2 + (le >> 3)]);
    uint32_t kdst0 = smem_u32(&ks[0][(le & 7) * KSTR2 + (le >> 3)]);
    uint32_t vdst0 = smem_u32(&vs[0][(tid - 256) & 63]);
    uint32_t gdst0 = smem_u32(&sgb[0][0]);
    const uint32_t QKROW = 8 * KSTR2 * 4;    // bytes per ring stage

    auto prefetch = [&](int t) {
        int st = t & (RD - 1);
        if (tid < 256) {
            cpa4(qdst0 + st * QKROW, qpl + (size_t)t * KDIM);
            cpa4(kdst0 + st * QKROW, kpl + (size_t)t * KDIM);
        } else if (tid < 320) {
            cpa4(vdst0 + st * 256, vpl + (size_t)t * VDIM);
        } else if (tid == 320) {
            cpa4(gdst0 + st * 8, gp + (size_t)t * Hh);
        } else if (tid == 321) {
            cpa4(gdst0 + st * 8 + 4, bp + (size_t)t * Hh);
        }
    };

    #pragma unroll
    for (int t = 0; t < RD - 1; t++) {
        prefetch(t);
        asm volatile("cp.async.commit_group;" ::: "memory");
    }

    u64t S2[16];
    #pragma unroll
    for (int j = 0; j < 16; j++) S2[j] = 0ull;
    u64t kreg2[16];

    for (int t = 0; t < Tt; t++) {
        asm volatile("cp.async.wait_group %0;" :: "n"(RD - 2) : "memory");
        __syncthreads();
        int st = t & (RD - 1);

        int tp = t + RD - 1;
        if (tp < Tt) prefetch(tp);
        asm volatile("cp.async.commit_group;" ::: "memory");

        float eg = expf(sgb[st][0]);
        float bt = sgb[st][1];
        u64t eg2; PACK2(eg2, eg, eg);

        // partial = sum over this lane's 32 k-elems of k*S (2 chains)
        u64t p2a = 0ull, p2b = 0ull;
        #pragma unroll
        for (int jj = 0; jj < 8; jj++) {
            ulonglong2 kv = *(const ulonglong2*)&ks[st][kb36 + 4 * jj];
            kreg2[2 * jj]     = kv.x;
            kreg2[2 * jj + 1] = kv.y;
            FMA2(p2a, kv.x, S2[2 * jj],     p2a);
            FMA2(p2b, kv.y, S2[2 * jj + 1], p2b);
        }
        ADD2(p2a, p2a, p2b);
        float plo, phi;
        UNPK2(plo, phi, p2a);
        float partial = plo + phi;
        partial += __shfl_xor_sync(0xffffffffu, partial, 1);
        partial += __shfl_xor_sync(0xffffffffu, partial, 2);
        partial += __shfl_xor_sync(0xffffffffu, partial, 4);
        float delta = (vs[st][vi] - eg * partial) * bt;
        u64t d2; PACK2(d2, delta, delta);

        // S = eg*S + k*delta ; opart = sum q*S
        u64t o2a = 0ull, o2b = 0ull;
        #pragma unroll
        for (int jj = 0; jj < 8; jj++) {
            ulonglong2 qv = *(const ulonglong2*)&qs[st][kb36 + 4 * jj];
            u64t t0, t1;
            MUL2(t0, kreg2[2 * jj],     d2);
            MUL2(t1, kreg2[2 * jj + 1], d2);
            FMA2(S2[2 * jj],     eg2, S2[2 * jj],     t0);
            FMA2(S2[2 * jj + 1], eg2, S2[2 * jj + 1], t1);
            FMA2(o2a, qv.x, S2[2 * jj],     o2a);
            FMA2(o2b, qv.y, S2[2 * jj + 1], o2b);
        }
        ADD2(o2a, o2a, o2b);
        float olo, ohi;
        UNPK2(olo, ohi, o2a);
        float opart = olo + ohi;
        opart += __shfl_xor_sync(0xffffffffu, opart, 1);
        opart += __shfl_xor_sync(0xffffffffu, opart, 2);
        opart += __shfl_xor_sync(0xffffffffu, opart, 4);
        if (kb == 0) o[((size_t)b * Tt + t) * VDIM + h * DVv + v0 + vi] = opart;
    }
}

// ---------------- gated RMSNorm + silu(gate) -> half ----------------
__global__ void rmsgate_kernel(const float* __restrict__ o, const __half* __restrict__ xall,
                               const float* __restrict__ onw, __half* __restrict__ oh) {
    int rowh = blockIdx.x;
    long row = rowh >> 2;
    int h = rowh & 3;
    const float* op = o + row * VDIM + h * DVv;
    const __half* gp = xall + row * (long)NQKVG + 4096 + h * DVv;
    __half* ohp = oh + row * VDIM + h * DVv;
    float v1 = op[threadIdx.x], v2 = op[threadIdx.x + 256];
    float ss = v1 * v1 + v2 * v2;
    __shared__ float sh[8];
    int lane = threadIdx.x & 31, wid = threadIdx.x >> 5;
    #pragma unroll
    for (int off = 16; off > 0; off >>= 1) ss += __shfl_xor_sync(0xffffffffu, ss, off);
    if (lane == 0) sh[wid] = ss;
    __syncthreads();
    if (threadIdx.x == 0) {
        float a = 0.f;
        #pragma unroll
        for (int i = 0; i < 8; i++) a += sh[i];
        sh[0] = a;
    }
    __syncthreads();
    float scale = rsqrtf(sh[0] * (1.0f / DVv) + 1e-5f);
    int c1 = threadIdx.x, c2 = threadIdx.x + 256;
    ohp[c1] = __float2half(v1 * scale * onw[c1] * siluf_(__half2float(gp[c1])));
    ohp[c2] = __float2half(v2 * scale * onw[c2] * siluf_(__half2float(gp[c2])));
}

// ---------------- launcher ----------------
extern "C" void kernel_launch(void* const* d_in, const int* in_sizes, int n_in,
                              void* d_out, int out_size) {
    const float* x        = (const float*)d_in[0];
    const float* Wq       = (const float*)d_in[1];
    const float* Wk       = (const float*)d_in[2];
    const float* Wv       = (const float*)d_in[3];
    const float* Wa       = (const float*)d_in[4];
    const float* Wb       = (const float*)d_in[5];
    const float* Wg       = (const float*)d_in[6];
    const float* conv_q_w = (const float*)d_in[7];
    const float* conv_k_w = (const float*)d_in[8];
    const float* conv_v_w = (const float*)d_in[9];
    const float* A_log    = (const float*)d_in[10];
    const float* dt_bias  = (const float*)d_in[11];
    const float* o_norm_w = (const float*)d_in[12];
    const float* Wo       = (const float*)d_in[13];
    const float* ln1_w    = (const float*)d_in[14];
    const float* ln1_b    = (const float*)d_in[15];
    const float* ln2_w    = (const float*)d_in[16];
    const float* ln2_b    = (const float*)d_in[17];
    const float* ffn_w1   = (const float*)d_in[18];
    const float* ffn_b1   = (const float*)d_in[19];
    const float* ffn_w2   = (const float*)d_in[20];
    const float* ffn_b2   = (const float*)d_in[21];
    float* out = (float*)d_out;

    __half *normh, *xallh, *oh, *hbufh, *ffn1h, *wth;
    float *q, *k, *v, *gg, *bb, *o, *x2;
    cudaGetSymbolAddress((void**)&normh, g_normh);
    cudaGetSymbolAddress((void**)&xallh, g_xallh);
    cudaGetSymbolAddress((void**)&q, g_q);
    cudaGetSymbolAddress((void**)&k, g_k);
    cudaGetSymbolAddress((void**)&v, g_v);
    cudaGetSymbolAddress((void**)&gg, g_gg);
    cudaGetSymbolAddress((void**)&bb, g_bb);
    cudaGetSymbolAddress((void**)&o, g_o);
    cudaGetSymbolAddress((void**)&oh, g_oh);
    cudaGetSymbolAddress((void**)&x2, g_x2);
    cudaGetSymbolAddress((void**)&hbufh, g_hbufh);
    cudaGetSymbolAddress((void**)&ffn1h, g_ffn1h);
    cudaGetSymbolAddress((void**)&wth, g_wth);

    cudaFuncSetAttribute(hgemm<2>, cudaFuncAttributeMaxDynamicSharedMemorySize, SMEM_DYN);
    cudaFuncSetAttribute(hgemm<3>, cudaFuncAttributeMaxDynamicSharedMemorySize, SMEM_DYN);
    cudaFuncSetAttribute(hgemm<4>, cudaFuncAttributeMaxDynamicSharedMemorySize, SMEM_DYN);
    cudaFuncSetAttribute(hgemm<5>, cudaFuncAttributeMaxDynamicSharedMemorySize, SMEM_DYN);

    // 0: all weight transposes
    transpose_all_kernel<<<16384, dim3(32, 8)>>>(Wq, Wk, Wv, Wg, Wo, ffn_w1, ffn_w2, wth);

    // 1: LN1 -> half
    ln_kernel<<<NROWS, 256>>>(x, ln1_w, ln1_b, normh);

    // 2: g/beta
    gbeta_kernel<<<NROWS / 8, 256>>>(normh, Wa, Wb, A_log, dt_bias, gg, bb);

    // 3: fused Q|K|V|G projection -> half
    hgemm<5><<<dim3(NQKVG/128, NROWS/128), 256, SMEM_DYN>>>(normh, wth + WT_QKVG, xallh,
                                                            NROWS, NQKVG, Dd, nullptr, nullptr);

    // 4: conv + silu + l2norm for q and k
    conv_l2_kernel<<<NROWS * Hh * 2, 128>>>(xallh, conv_q_w, conv_k_w, q, k);
    // 5: conv + silu for v
    {
        long tv2 = (long)NROWS * (VDIM / 2);
        conv_silu_kernel<<<(unsigned)((tv2 + 255) / 256), 256>>>(xallh, 2048, conv_v_w, v, tv2);
    }

    // 6: scan (512 threads, 8-lane k-split)
    scan_kernel<<<Bb * Hh * 8, 512>>>(q, k, v, gg, bb, o);

    // 7: gated RMSNorm -> half
    rmsgate_kernel<<<NROWS * Hh, 256>>>(o, xallh, o_norm_w, oh);

    // 8: x2 = x + oh @ WoT
    hgemm<3><<<dim3(Dd/128, NROWS/128), 256, SMEM_DYN>>>(oh, wth + WT_O, x2,
                                                         NROWS, Dd, VDIM, nullptr, x);

    // 9: LN2 + FFN
    ln_kernel<<<NROWS, 256>>>(x2, ln2_w, ln2_b, hbufh);
    hgemm<2><<<dim3(FFND/128, NROWS/128), 256, SMEM_DYN>>>(hbufh, wth + WT_F1, ffn1h,
                                                           NROWS, FFND, Dd, ffn_b1, nullptr);
    hgemm<4><<<dim3(Dd/128, NROWS/128), 256, SMEM_DYN>>>(ffn1h, wth + WT_F2, out,
                                                         NROWS, Dd, FFND, ffn_b2, x2);
}

// round 13
// speedup vs baseline: 1.0162x; 1.0162x over previous
#include <cuda_runtime.h>
#include <cuda_fp16.h>
#include <math.h>
#include <stdint.h>

#define Bb   4
#define Tt   2048
#define Dd   1024
#define Hh   4
#define DKk  256
#define DVv  512
#define KDIM 1024
#define VDIM 2048
#define FFND 4096
#define NROWS (Bb*Tt)   /* 8192 */
#define NQKVG 6144

// ---------------- scratch ----------------
__device__ __half  g_normh[NROWS*Dd];
__device__ __half  g_xallh[(size_t)NROWS*NQKVG];
__device__ float   g_q[NROWS*KDIM];
__device__ float   g_k[NROWS*KDIM];
__device__ float   g_v[NROWS*VDIM];
__device__ float   g_gg[NROWS*Hh];
__device__ float   g_bb[NROWS*Hh];
__device__ float   g_o[NROWS*VDIM];
__device__ __half  g_oh[NROWS*VDIM];
__device__ float   g_x2[NROWS*Dd];
__device__ __half  g_hbufh[NROWS*Dd];
__device__ __half  g_ffn1h[(size_t)NROWS*FFND];
__device__ __half  g_wth[16*1024*1024];
#define WT_QKVG 0
#define WT_O   (6*1024*1024)
#define WT_F1  (8*1024*1024)
#define WT_F2  (12*1024*1024)

// ---------------- helpers ----------------
__device__ __forceinline__ float sigmoidf_(float x) { return 1.0f / (1.0f + expf(-x)); }
__device__ __forceinline__ float siluf_(float x)    { return x * sigmoidf_(x); }
__device__ __forceinline__ float geluf_(float x)    { return 0.5f * x * (1.0f + erff(x * 0.70710678118654752f)); }
__device__ __forceinline__ float softplusf_(float x){ return (x > 20.0f) ? x : log1pf(expf(x)); }
__device__ __forceinline__ uint32_t smem_u32(const void* p) {
    uint32_t a;
    asm("{ .reg .u64 t; cvta.to.shared.u64 t, %1; cvt.u32.u64 %0, t; }" : "=r"(a) : "l"(p));
    return a;
}
__device__ __forceinline__ void cpa16(uint32_t dst, const void* src) {
    asm volatile("cp.async.cg.shared.global [%0], [%1], 16;" :: "r"(dst), "l"(src));
}
__device__ __forceinline__ void cpa4(uint32_t dst, const void* src) {
    asm volatile("cp.async.ca.shared.global [%0], [%1], 4;" :: "r"(dst), "l"(src));
}
__device__ __forceinline__ void ldm4(uint32_t* r, uint32_t addr) {
    asm volatile("ldmatrix.sync.aligned.m8n8.x4.shared.b16 {%0,%1,%2,%3}, [%4];"
        : "=r"(r[0]), "=r"(r[1]), "=r"(r[2]), "=r"(r[3]) : "r"(addr));
}
#define SWZ(o) ((o) ^ (((o) >> 3) & 0x70))

typedef unsigned long long u64t;
#define FMA2(d, a, b, c) asm("fma.rn.f32x2 %0, %1, %2, %3;" : "=l"(d) : "l"(a), "l"(b), "l"(c))
#define MUL2(d, a, b)    asm("mul.rn.f32x2 %0, %1, %2;"     : "=l"(d) : "l"(a), "l"(b))
#define ADD2(d, a, b)    asm("add.rn.f32x2 %0, %1, %2;"     : "=l"(d) : "l"(a), "l"(b))
#define PACK2(d, lo, hi) asm("mov.b64 %0, {%1, %2};" : "=l"(d) : "f"(lo), "f"(hi))
#define UNPK2(lo, hi, s) asm("mov.b64 {%0, %1}, %2;" : "=f"(lo), "=f"(hi) : "l"(s))

// ---------------- ONE fused transpose launch: 7 matrices, src[K,N] -> half dst[N,K] ----------------
__global__ void transpose_all_kernel(const float* __restrict__ Wq, const float* __restrict__ Wk,
                                     const float* __restrict__ Wv, const float* __restrict__ Wg,
                                     const float* __restrict__ Wo, const float* __restrict__ F1,
                                     const float* __restrict__ F2, __half* __restrict__ wth) {
    const int cum[7] = {1024, 2048, 4096, 6144, 8192, 12288, 16384};
    const int Ks[7]  = {1024, 1024, 1024, 1024, 2048, 1024, 4096};
    const int Ns[7]  = {1024, 1024, 2048, 2048, 1024, 4096, 1024};
    const size_t doff[7] = {0, 1024*1024, 2*1024*1024, 4*1024*1024,
                            6*1024*1024, 8*1024*1024, 12*1024*1024};
    int bid = blockIdx.x;
    int m = 0;
    #pragma unroll
    for (int i = 0; i < 7; i++) if (bid >= cum[i]) m = i + 1;
    int lt = bid - (m ? cum[m - 1] : 0);
    const float* srcs[7] = {Wq, Wk, Wv, Wg, Wo, F1, F2};
    const float* src = srcs[m];
    __half* dst = wth + doff[m];
    int K = Ks[m], N = Ns[m];
    int tilesN = N >> 5;
    int nb = (lt % tilesN) * 32, kb = (lt / tilesN) * 32;

    __shared__ float t[32][33];
    int x = threadIdx.x, y = threadIdx.y;
    #pragma unroll
    for (int i = 0; i < 4; i++)
        t[y + 8 * i][x] = src[(size_t)(kb + y + 8 * i) * N + nb + x];
    __syncthreads();
    #pragma unroll
    for (int i = 0; i < 4; i++)
        dst[(size_t)(nb + y + 8 * i) * K + kb + x] = __float2half(t[x][y + 8 * i]);
}

// ---------------- fp16 mma.sync GEMM 128x128, 2-stage cp.async, 2 CTAs/SM ----------------
// EPI: 2 half bias+gelu | 3 float +res | 4 float bias+res | 5 half none
#define STG_BYTES 32768
#define SMEM_DYN (2 * STG_BYTES)

template<int EPI>
__global__ void __launch_bounds__(256)
hgemm(const __half* __restrict__ A, const __half* __restrict__ Bt, void* __restrict__ Cv,
      int M_, int N_, int K_, const float* __restrict__ bias, const float* __restrict__ res) {
    extern __shared__ char sm[];
    uint32_t sbase = smem_u32(sm);
    int tid = threadIdx.x, wid = tid >> 5, lane = tid & 31;
    int g = lane >> 2, tg = lane & 3;
    int bm = blockIdx.y * 128, bn = blockIdx.x * 128;
    int wm = (wid & 1) * 64, wn = (wid >> 1) * 32;

    int lrow = tid >> 1, lc0 = (tid & 1) * 4;
    const __half* gA = A + (size_t)(bm + lrow) * K_ + lc0 * 8;
    const __half* gB = Bt + (size_t)(bn + lrow) * K_ + lc0 * 8;
    uint32_t sAo[4], sBo[4];
    #pragma unroll
    for (int i = 0; i < 4; i++) {
        uint32_t off = lrow * 128 + (lc0 + i) * 16;
        sAo[i] = SWZ(off);
        sBo[i] = 16384 + SWZ(off);
    }
    auto load_stage = [&](int chunk, int stage) {
        uint32_t st = sbase + stage * STG_BYTES;
        const __half* a = gA + chunk * 64;
        const __half* b = gB + chunk * 64;
        #pragma unroll
        for (int i = 0; i < 4; i++) cpa16(st + sAo[i], a + i * 8);
        #pragma unroll
        for (int i = 0; i < 4; i++) cpa16(st + sBo[i], b + i * 8);
        asm volatile("cp.async.commit_group;" ::: "memory");
    };

    int arow = lane & 15;
    int acb  = (lane >> 4) * 16;
    int bsel = lane >> 3;
    int brow = (lane & 7) + ((bsel & 2) ? 8 : 0);
    int bcb  = (bsel & 1) * 16;
    uint32_t aBase[4], bBase[2];
    #pragma unroll
    for (int mt = 0; mt < 4; mt++)
        aBase[mt] = (wm + mt * 16 + arow) * 128 + acb;
    #pragma unroll
    for (int np = 0; np < 2; np++)
        bBase[np] = 16384 + (wn + np * 16 + brow) * 128 + bcb;

    float acc[4][4][4];
    #pragma unroll
    for (int i = 0; i < 4; i++)
        #pragma unroll
        for (int j = 0; j < 4; j++)
            #pragma unroll
            for (int r = 0; r < 4; r++) acc[i][j][r] = 0.f;

    const int NK = K_ >> 6;
    load_stage(0, 0);
    load_stage(1, 1);

    for (int k = 0; k < NK; k++) {
        int sk = k & 1;
        asm volatile("cp.async.wait_group %0;" :: "n"(1) : "memory");
        __syncthreads();
        uint32_t st = sbase + sk * STG_BYTES;

        #pragma unroll
        for (int kk = 0; kk < 4; kk++) {
            int kbyte = kk * 32;
            uint32_t af[4][4], bf[4][2];
            #pragma unroll
            for (int mt = 0; mt < 4; mt++)
                ldm4(af[mt], st + SWZ(aBase[mt] + kbyte));
            #pragma unroll
            for (int np = 0; np < 2; np++) {
                uint32_t r4[4];
                ldm4(r4, st + SWZ(bBase[np] + kbyte));
                bf[2 * np][0] = r4[0]; bf[2 * np][1] = r4[1];
                bf[2 * np + 1][0] = r4[2]; bf[2 * np + 1][1] = r4[3];
            }
            #pragma unroll
            for (int mt = 0; mt < 4; mt++)
                #pragma unroll
                for (int nt = 0; nt < 4; nt++)
                    asm volatile(
                        "mma.sync.aligned.m16n8k16.row.col.f32.f16.f16.f32 "
                        "{%0,%1,%2,%3}, {%4,%5,%6,%7}, {%8,%9}, {%0,%1,%2,%3};"
                        : "+f"(acc[mt][nt][0]), "+f"(acc[mt][nt][1]),
                          "+f"(acc[mt][nt][2]), "+f"(acc[mt][nt][3])
                        : "r"(af[mt][0]), "r"(af[mt][1]), "r"(af[mt][2]), "r"(af[mt][3]),
                          "r"(bf[nt][0]), "r"(bf[nt][1]));
        }
        __syncthreads();
        if (k + 2 < NK) load_stage(k + 2, sk);
        else asm volatile("cp.async.commit_group;" ::: "memory");
    }

    float* Cf = (float*)Cv;
    __half* Ch = (__half*)Cv;
    #pragma unroll
    for (int mt = 0; mt < 4; mt++) {
        #pragma unroll
        for (int nt = 0; nt < 4; nt++) {
            int col = bn + wn + nt * 8 + 2 * tg;
            float b0 = 0.f, b1 = 0.f;
            if (EPI == 2 || EPI == 4) { b0 = bias[col]; b1 = bias[col + 1]; }
            #pragma unroll
            for (int h2 = 0; h2 < 2; h2++) {
                int row = bm + wm + mt * 16 + g + h2 * 8;
                float v0 = acc[mt][nt][2 * h2], v1 = acc[mt][nt][2 * h2 + 1];
                if (EPI == 2 || EPI == 4) { v0 += b0; v1 += b1; }
                if (EPI == 2 || EPI == 5) {
                    __half2 hv;
                    hv.x = __float2half(EPI == 2 ? geluf_(v0) : v0);
                    hv.y = __float2half(EPI == 2 ? geluf_(v1) : v1);
                    *(__half2*)(Ch + (size_t)row * N_ + col) = hv;
                } else {
                    if (EPI == 3 || EPI == 4) {
                        float2 rr = *(const float2*)(res + (size_t)row * N_ + col);
                        v0 += rr.x; v1 += rr.y;
                    }
                    float2 o2; o2.x = v0; o2.y = v1;
                    *(float2*)(Cf + (size_t)row * N_ + col) = o2;
                }
            }
        }
    }
}

// ---------------- LayerNorm -> half ----------------
__global__ void ln_kernel(const float* __restrict__ x, const float* __restrict__ w,
                          const float* __restrict__ b, __half* __restrict__ out) {
    int row = blockIdx.x;
    const float* xr = x + (size_t)row * Dd;
    float s1 = 0.f, s2 = 0.f;
    float vals[4];
    #pragma unroll
    for (int i = 0; i < 4; i++) {
        float v = xr[threadIdx.x + i * 256];
        vals[i] = v; s1 += v; s2 += v * v;
    }
    __shared__ float sh[2][8];
    int lane = threadIdx.x & 31, wid = threadIdx.x >> 5;
    #pragma unroll
    for (int off = 16; off > 0; off >>= 1) {
        s1 += __shfl_xor_sync(0xffffffffu, s1, off);
        s2 += __shfl_xor_sync(0xffffffffu, s2, off);
    }
    if (lane == 0) { sh[0][wid] = s1; sh[1][wid] = s2; }
    __syncthreads();
    if (threadIdx.x == 0) {
        float a = 0.f, c = 0.f;
        #pragma unroll
        for (int i = 0; i < 8; i++) { a += sh[0][i]; c += sh[1][i]; }
        sh[0][0] = a; sh[1][0] = c;
    }
    __syncthreads();
    float mean = sh[0][0] * (1.0f / Dd);
    float var  = sh[1][0] * (1.0f / Dd) - mean * mean;
    float inv  = rsqrtf(var + 1e-5f);
    #pragma unroll
    for (int i = 0; i < 4; i++) {
        int c = threadIdx.x + i * 256;
        out[(size_t)row * Dd + c] = __float2half((vals[i] - mean) * inv * w[c] + b[c]);
    }
}

// ---------------- g / beta ----------------
__global__ void gbeta_kernel(const __half* __restrict__ normed, const float* __restrict__ Wa,
                             const float* __restrict__ Wb, const float* __restrict__ A_log,
                             const float* __restrict__ dt_bias, float* __restrict__ g,
                             float* __restrict__ beta) {
    int row = blockIdx.x * 8 + (threadIdx.x >> 5);
    int lane = threadIdx.x & 31;
    const __half* xr = normed + (size_t)row * Dd;
    float acc[8];
    #pragma unroll
    for (int j = 0; j < 8; j++) acc[j] = 0.f;
    for (int k = lane; k < Dd; k += 32) {
        float xv = __half2float(xr[k]);
        const float* wa = Wa + k * 4;
        const float* wb = Wb + k * 4;
        #pragma unroll
        for (int j = 0; j < 4; j++) { acc[j] += xv * wa[j]; acc[4 + j] += xv * wb[j]; }
    }
    #pragma unroll
    for (int off = 16; off > 0; off >>= 1)
        #pragma unroll
        for (int j = 0; j < 8; j++) acc[j] += __shfl_xor_sync(0xffffffffu, acc[j], off);
    if (lane < 4) {
        float xa = acc[lane] + dt_bias[lane];
        g[row * 4 + lane] = -expf(A_log[lane]) * softplusf_(xa);
        beta[row * 4 + lane] = sigmoidf_(acc[4 + lane]);
    }
}

// ---------------- fused conv+SiLU+l2norm for q AND k (half2 vectorized) ----------------
__global__ void conv_l2_kernel(const __half* __restrict__ xall,
                               const float* __restrict__ wq, const float* __restrict__ wk,
                               float* __restrict__ qout, float* __restrict__ kout) {
    int bid = blockIdx.x;
    bool isq = bid < NROWS * Hh;
    int rowh = isq ? bid : bid - NROWS * Hh;
    long row = rowh >> 2;
    int h = rowh & 3;
    int t = (int)(row & (Tt - 1));
    long bbase = row - t;
    int c = h * DKk + threadIdx.x * 2;
    int coff = isq ? 0 : 1024;
    const float* w = isq ? wq : wk;
    float wA[2][4] = {{w[c*4+0], w[c*4+1], w[c*4+2], w[c*4+3]},
                      {w[c*4+4], w[c*4+5], w[c*4+6], w[c*4+7]}};
    float a0 = 0.f, a1 = 0.f;
    #pragma unroll
    for (int i = 0; i < 4; i++) {
        int tt = t - 3 + i;
        if (tt >= 0) {
            __half2 hv = *(const __half2*)(xall + (bbase + tt) * (long)NQKVG + coff + c);
            float2 fv = __half22float2(hv);
            a0 += fv.x * wA[0][i];
            a1 += fv.y * wA[1][i];
        }
    }
    float v0 = siluf_(a0), v1 = siluf_(a1);
    float ss = v0 * v0 + v1 * v1;
    __shared__ float sh[4];
    int lane = threadIdx.x & 31, wid = threadIdx.x >> 5;
    #pragma unroll
    for (int off = 16; off > 0; off >>= 1) ss += __shfl_xor_sync(0xffffffffu, ss, off);
    if (lane == 0) sh[wid] = ss;
    __syncthreads();
    if (threadIdx.x == 0) sh[0] = sh[0] + sh[1] + sh[2] + sh[3];
    __syncthreads();
    float sc = (isq ? 0.0625f : 1.0f) * rsqrtf(sh[0] + 1e-6f);
    float* outp = isq ? qout : kout;
    float2 o2; o2.x = v0 * sc; o2.y = v1 * sc;
    *(float2*)(outp + row * KDIM + c) = o2;
}

// ---------------- conv + SiLU for V (half2 vectorized) ----------------
__global__ void conv_silu_kernel(const __half* __restrict__ x, int coff,
                                 const float* __restrict__ w,
                                 float* __restrict__ y, long total2) {
    long idx = (long)blockIdx.x * blockDim.x + threadIdx.x;
    if (idx >= total2) return;
    int c = (int)(idx % (VDIM / 2)) * 2;
    long bt = idx / (VDIM / 2);
    int t = (int)(bt % Tt);
    long bbase = (bt / Tt) * Tt;
    const float* w4 = w + c * 4;
    float a0 = 0.f, a1 = 0.f;
    #pragma unroll
    for (int i = 0; i < 4; i++) {
        int tt = t - 3 + i;
        if (tt >= 0) {
            __half2 hv = *(const __half2*)(x + (bbase + tt) * (long)NQKVG + coff + c);
            float2 fv = __half22float2(hv);
            a0 += fv.x * w4[i];
            a1 += fv.y * w4[4 + i];
        }
    }
    float2 o2; o2.x = siluf_(a0); o2.y = siluf_(a1);
    *(float2*)(y + bt * VDIM + c) = o2;
}

// ---------------- gated delta rule scan: normalized state (25% fewer FMA2) ----------------
// S_true = P * Shat ; per step: P *= eg ; mem = P*(k.Shat) ; delta = beta*(v-mem);
// Shat += k*(delta/P) ; o = P*(q.Shat).  Uniform renorm when P < 1e-10.
#define KSTR 68
#define RD 8
__global__ void __launch_bounds__(256)
scan_kernel(const float* __restrict__ q, const float* __restrict__ k, const float* __restrict__ v,
            const float* __restrict__ g, const float* __restrict__ beta, float* __restrict__ o) {
    int b  = blockIdx.x >> 5;
    int h  = (blockIdx.x >> 3) & 3;
    int sl = blockIdx.x & 7;
    int v0 = sl * 64;
    int tid = threadIdx.x;
    int kb = tid & 3, vi = tid >> 2;
    int kb68 = kb * KSTR;

    __shared__ float qs[RD][4 * KSTR], ks[RD][4 * KSTR], vs[RD][64], sgb[RD][2];

    const float* qp = q + (size_t)b * Tt * KDIM + h * DKk + tid;
    const float* kp = k + (size_t)b * Tt * KDIM + h * DKk + tid;
    const float* vp = v + (size_t)b * Tt * VDIM + h * DVv + v0 + tid;
    const float* gp = g + (size_t)b * Tt * Hh + h;
    const float* bp = beta + (size_t)b * Tt * Hh + h;

    uint32_t qdst0 = smem_u32(&qs[0][kb * KSTR + vi]);
    uint32_t kdst0 = smem_u32(&ks[0][kb * KSTR + vi]);
    uint32_t vdst0 = smem_u32(&vs[0][tid & 63]);
    uint32_t gdst0 = smem_u32(&sgb[0][0]);
    const uint32_t QKROW = 4 * KSTR * 4;

    auto prefetch = [&](int t) {
        int st = t & (RD - 1);
        cpa4(qdst0 + st * QKROW, qp + (size_t)t * KDIM);
        cpa4(kdst0 + st * QKROW, kp + (size_t)t * KDIM);
        if (tid < 64)       cpa4(vdst0 + st * 256, vp + (size_t)t * VDIM);
        else if (tid == 64) cpa4(gdst0 + st * 8,     gp + (size_t)t * Hh);
        else if (tid == 65) cpa4(gdst0 + st * 8 + 4, bp + (size_t)t * Hh);
    };

    #pragma unroll
    for (int t = 0; t < RD - 1; t++) {
        prefetch(t);
        asm volatile("cp.async.commit_group;" ::: "memory");
    }

    u64t S2[32];
    #pragma unroll
    for (int j = 0; j < 32; j++) S2[j] = 0ull;
    u64t kreg2[32];
    float P = 1.0f;

    for (int t = 0; t < Tt; t++) {
        asm volatile("cp.async.wait_group %0;" :: "n"(RD - 2) : "memory");
        __syncthreads();
        int st = t & (RD - 1);

        int tp = t + RD - 1;
        if (tp < Tt) prefetch(tp);
        asm volatile("cp.async.commit_group;" ::: "memory");

        float eg = expf(sgb[st][0]);
        float bt = sgb[st][1];
        P *= eg;
        if (P < 1e-10f) {                    // uniform across block (same g stream)
            u64t pp; PACK2(pp, P, P);
            #pragma unroll
            for (int j = 0; j < 32; j++) MUL2(S2[j], S2[j], pp);
            P = 1.0f;
        }

        // pk = k . Shat  (4 chains)
        u64t p2a = 0ull, p2b = 0ull;
        #pragma unroll
        for (int jj = 0; jj < 16; jj++) {
            ulonglong2 kv = *(const ulonglong2*)&ks[st][kb68 + 4 * jj];
            kreg2[2 * jj]     = kv.x;
            kreg2[2 * jj + 1] = kv.y;
            FMA2(p2a, kv.x, S2[2 * jj],     p2a);
            FMA2(p2b, kv.y, S2[2 * jj + 1], p2b);
        }
        ADD2(p2a, p2a, p2b);
        float plo, phi;
        UNPK2(plo, phi, p2a);
        float partial = plo + phi;
        partial += __shfl_xor_sync(0xffffffffu, partial, 1);
        partial += __shfl_xor_sync(0xffffffffu, partial, 2);
        float delta = (vs[st][vi] - P * partial) * bt;
        float dprime = delta / P;
        u64t d2; PACK2(d2, dprime, dprime);

        // Shat += k * dprime ; opart = q . Shat_new
        u64t o2a = 0ull, o2b = 0ull;
        #pragma unroll
        for (int jj = 0; jj < 16; jj++) {
            ulonglong2 qv = *(const ulonglong2*)&qs[st][kb68 + 4 * jj];
            FMA2(S2[2 * jj],     kreg2[2 * jj],     d2, S2[2 * jj]);
            FMA2(S2[2 * jj + 1], kreg2[2 * jj + 1], d2, S2[2 * jj + 1]);
            FMA2(o2a, qv.x, S2[2 * jj],     o2a);
            FMA2(o2b, qv.y, S2[2 * jj + 1], o2b);
        }
        ADD2(o2a, o2a, o2b);
        float olo, ohi;
        UNPK2(olo, ohi, o2a);
        float opart = olo + ohi;
        opart += __shfl_xor_sync(0xffffffffu, opart, 1);
        opart += __shfl_xor_sync(0xffffffffu, opart, 2);
        if (kb == 0) o[((size_t)b * Tt + t) * VDIM + h * DVv + v0 + vi] = P * opart;
    }
}

// ---------------- gated RMSNorm + silu(gate) -> half ----------------
__global__ void rmsgate_kernel(const float* __restrict__ o, const __half* __restrict__ xall,
                               const float* __restrict__ onw, __half* __restrict__ oh) {
    int rowh = blockIdx.x;
    long row = rowh >> 2;
    int h = rowh & 3;
    const float* op = o + row * VDIM + h * DVv;
    const __half* gp = xall + row * (long)NQKVG + 4096 + h * DVv;
    __half* ohp = oh + row * VDIM + h * DVv;
    float v1 = op[threadIdx.x], v2 = op[threadIdx.x + 256];
    float ss = v1 * v1 + v2 * v2;
    __shared__ float sh[8];
    int lane = threadIdx.x & 31, wid = threadIdx.x >> 5;
    #pragma unroll
    for (int off = 16; off > 0; off >>= 1) ss += __shfl_xor_sync(0xffffffffu, ss, off);
    if (lane == 0) sh[wid] = ss;
    __syncthreads();
    if (threadIdx.x == 0) {
        float a = 0.f;
        #pragma unroll
        for (int i = 0; i < 8; i++) a += sh[i];
        sh[0] = a;
    }
    __syncthreads();
    float scale = rsqrtf(sh[0] * (1.0f / DVv) + 1e-5f);
    int c1 = threadIdx.x, c2 = threadIdx.x + 256;
    ohp[c1] = __float2half(v1 * scale * onw[c1] * siluf_(__half2float(gp[c1])));
    ohp[c2] = __float2half(v2 * scale * onw[c2] * siluf_(__half2float(gp[c2])));
}

// ---------------- launcher ----------------
extern "C" void kernel_launch(void* const* d_in, const int* in_sizes, int n_in,
                              void* d_out, int out_size) {
    const float* x        = (const float*)d_in[0];
    const float* Wq       = (const float*)d_in[1];
    const float* Wk       = (const float*)d_in[2];
    const float* Wv       = (const float*)d_in[3];
    const float* Wa       = (const float*)d_in[4];
    const float* Wb       = (const float*)d_in[5];
    const float* Wg       = (const float*)d_in[6];
    const float* conv_q_w = (const float*)d_in[7];
    const float* conv_k_w = (const float*)d_in[8];
    const float* conv_v_w = (const float*)d_in[9];
    const float* A_log    = (const float*)d_in[10];
    const float* dt_bias  = (const float*)d_in[11];
    const float* o_norm_w = (const float*)d_in[12];
    const float* Wo       = (const float*)d_in[13];
    const float* ln1_w    = (const float*)d_in[14];
    const float* ln1_b    = (const float*)d_in[15];
    const float* ln2_w    = (const float*)d_in[16];
    const float* ln2_b    = (const float*)d_in[17];
    const float* ffn_w1   = (const float*)d_in[18];
    const float* ffn_b1   = (const float*)d_in[19];
    const float* ffn_w2   = (const float*)d_in[20];
    const float* ffn_b2   = (const float*)d_in[21];
    float* out = (float*)d_out;

    __half *normh, *xallh, *oh, *hbufh, *ffn1h, *wth;
    float *q, *k, *v, *gg, *bb, *o, *x2;
    cudaGetSymbolAddress((void**)&normh, g_normh);
    cudaGetSymbolAddress((void**)&xallh, g_xallh);
    cudaGetSymbolAddress((void**)&q, g_q);
    cudaGetSymbolAddress((void**)&k, g_k);
    cudaGetSymbolAddress((void**)&v, g_v);
    cudaGetSymbolAddress((void**)&gg, g_gg);
    cudaGetSymbolAddress((void**)&bb, g_bb);
    cudaGetSymbolAddress((void**)&o, g_o);
    cudaGetSymbolAddress((void**)&oh, g_oh);
    cudaGetSymbolAddress((void**)&x2, g_x2);
    cudaGetSymbolAddress((void**)&hbufh, g_hbufh);
    cudaGetSymbolAddress((void**)&ffn1h, g_ffn1h);
    cudaGetSymbolAddress((void**)&wth, g_wth);

    cudaFuncSetAttribute(hgemm<2>, cudaFuncAttributeMaxDynamicSharedMemorySize, SMEM_DYN);
    cudaFuncSetAttribute(hgemm<3>, cudaFuncAttributeMaxDynamicSharedMemorySize, SMEM_DYN);
    cudaFuncSetAttribute(hgemm<4>, cudaFuncAttributeMaxDynamicSharedMemorySize, SMEM_DYN);
    cudaFuncSetAttribute(hgemm<5>, cudaFuncAttributeMaxDynamicSharedMemorySize, SMEM_DYN);

    // 0: all weight transposes
    transpose_all_kernel<<<16384, dim3(32, 8)>>>(Wq, Wk, Wv, Wg, Wo, ffn_w1, ffn_w2, wth);

    // 1: LN1 -> half
    ln_kernel<<<NROWS, 256>>>(x, ln1_w, ln1_b, normh);

    // 2: g/beta
    gbeta_kernel<<<NROWS / 8, 256>>>(normh, Wa, Wb, A_log, dt_bias, gg, bb);

    // 3: fused Q|K|V|G projection -> half
    hgemm<5><<<dim3(NQKVG/128, NROWS/128), 256, SMEM_DYN>>>(normh, wth + WT_QKVG, xallh,
                                                            NROWS, NQKVG, Dd, nullptr, nullptr);

    // 4: conv + silu + l2norm for q and k
    conv_l2_kernel<<<NROWS * Hh * 2, 128>>>(xallh, conv_q_w, conv_k_w, q, k);
    // 5: conv + silu for v
    {
        long tv2 = (long)NROWS * (VDIM / 2);
        conv_silu_kernel<<<(unsigned)((tv2 + 255) / 256), 256>>>(xallh, 2048, conv_v_w, v, tv2);
    }

    // 6: scan (normalized-state)
    scan_kernel<<<Bb * Hh * 8, 256>>>(q, k, v, gg, bb, o);

    // 7: gated RMSNorm -> half
    rmsgate_kernel<<<NROWS * Hh, 256>>>(o, xallh, o_norm_w, oh);

    // 8: x2 = x + oh @ WoT
    hgemm<3><<<dim3(Dd/128, NROWS/128), 256, SMEM_DYN>>>(oh, wth + WT_O, x2,
                                                         NROWS, Dd, VDIM, nullptr, x);

    // 9: LN2 + FFN
    ln_kernel<<<NROWS, 256>>>(x2, ln2_w, ln2_b, hbufh);
    hgemm<2><<<dim3(FFND/128, NROWS/128), 256, SMEM_DYN>>>(hbufh, wth + WT_F1, ffn1h,
                                                           NROWS, FFND, Dd, ffn_b1, nullptr);
    hgemm<4><<<dim3(Dd/128, NROWS/128), 256, SMEM_DYN>>>(ffn1h, wth + WT_F2, out,
                                                         NROWS, Dd, FFND, ffn_b2, x2);
}

// round 14
// speedup vs baseline: 1.0390x; 1.0224x over previous
#include <cuda_runtime.h>
#include <cuda_fp16.h>
#include <math.h>
#include <stdint.h>

#define Bb   4
#define Tt   2048
#define Dd   1024
#define Hh   4
#define DKk  256
#define DVv  512
#define KDIM 1024
#define VDIM 2048
#define FFND 4096
#define NROWS (Bb*Tt)   /* 8192 */
#define NQKVG 6144

// ---------------- scratch ----------------
__device__ __half  g_normh[NROWS*Dd];
__device__ __half  g_xallh[(size_t)NROWS*NQKVG];
__device__ float   g_q[NROWS*KDIM];
__device__ float   g_k[NROWS*KDIM];
__device__ float   g_v[NROWS*VDIM];
__device__ float   g_gg[NROWS*Hh];
__device__ float   g_bb[NROWS*Hh];
__device__ float   g_o[NROWS*VDIM];
__device__ __half  g_oh[NROWS*VDIM];
__device__ float   g_x2[NROWS*Dd];
__device__ __half  g_hbufh[NROWS*Dd];
__device__ __half  g_ffn1h[(size_t)NROWS*FFND];
__device__ __half  g_wth[16*1024*1024];
#define WT_QKVG 0
#define WT_O   (6*1024*1024)
#define WT_F1  (8*1024*1024)
#define WT_F2  (12*1024*1024)

// ---------------- helpers ----------------
__device__ __forceinline__ float sigmoidf_(float x) { return 1.0f / (1.0f + expf(-x)); }
__device__ __forceinline__ float siluf_(float x)    { return x * sigmoidf_(x); }
__device__ __forceinline__ float geluf_(float x)    { return 0.5f * x * (1.0f + erff(x * 0.70710678118654752f)); }
__device__ __forceinline__ float softplusf_(float x){ return (x > 20.0f) ? x : log1pf(expf(x)); }
__device__ __forceinline__ uint32_t smem_u32(const void* p) {
    uint32_t a;
    asm("{ .reg .u64 t; cvta.to.shared.u64 t, %1; cvt.u32.u64 %0, t; }" : "=r"(a) : "l"(p));
    return a;
}
__device__ __forceinline__ void cpa16(uint32_t dst, const void* src) {
    asm volatile("cp.async.cg.shared.global [%0], [%1], 16;" :: "r"(dst), "l"(src));
}
__device__ __forceinline__ void cpa4(uint32_t dst, const void* src) {
    asm volatile("cp.async.ca.shared.global [%0], [%1], 4;" :: "r"(dst), "l"(src));
}
__device__ __forceinline__ void ldm4(uint32_t* r, uint32_t addr) {
    asm volatile("ldmatrix.sync.aligned.m8n8.x4.shared.b16 {%0,%1,%2,%3}, [%4];"
        : "=r"(r[0]), "=r"(r[1]), "=r"(r[2]), "=r"(r[3]) : "r"(addr));
}
#define SWZ(o) ((o) ^ (((o) >> 3) & 0x70))

typedef unsigned long long u64t;
#define FMA2(d, a, b, c) asm("fma.rn.f32x2 %0, %1, %2, %3;" : "=l"(d) : "l"(a), "l"(b), "l"(c))
#define MUL2(d, a, b)    asm("mul.rn.f32x2 %0, %1, %2;"     : "=l"(d) : "l"(a), "l"(b))
#define ADD2(d, a, b)    asm("add.rn.f32x2 %0, %1, %2;"     : "=l"(d) : "l"(a), "l"(b))
#define PACK2(d, lo, hi) asm("mov.b64 %0, {%1, %2};" : "=l"(d) : "f"(lo), "f"(hi))
#define UNPK2(lo, hi, s) asm("mov.b64 {%0, %1}, %2;" : "=f"(lo), "=f"(hi) : "l"(s))

// ---------------- ONE fused transpose launch: 7 matrices, src[K,N] -> half dst[N,K] ----------------
__global__ void transpose_all_kernel(const float* __restrict__ Wq, const float* __restrict__ Wk,
                                     const float* __restrict__ Wv, const float* __restrict__ Wg,
                                     const float* __restrict__ Wo, const float* __restrict__ F1,
                                     const float* __restrict__ F2, __half* __restrict__ wth) {
    const int cum[7] = {1024, 2048, 4096, 6144, 8192, 12288, 16384};
    const int Ks[7]  = {1024, 1024, 1024, 1024, 2048, 1024, 4096};
    const int Ns[7]  = {1024, 1024, 2048, 2048, 1024, 4096, 1024};
    const size_t doff[7] = {0, 1024*1024, 2*1024*1024, 4*1024*1024,
                            6*1024*1024, 8*1024*1024, 12*1024*1024};
    int bid = blockIdx.x;
    int m = 0;
    #pragma unroll
    for (int i = 0; i < 7; i++) if (bid >= cum[i]) m = i + 1;
    int lt = bid - (m ? cum[m - 1] : 0);
    const float* srcs[7] = {Wq, Wk, Wv, Wg, Wo, F1, F2};
    const float* src = srcs[m];
    __half* dst = wth + doff[m];
    int K = Ks[m], N = Ns[m];
    int tilesN = N >> 5;
    int nb = (lt % tilesN) * 32, kb = (lt / tilesN) * 32;

    __shared__ float t[32][33];
    int x = threadIdx.x, y = threadIdx.y;
    #pragma unroll
    for (int i = 0; i < 4; i++)
        t[y + 8 * i][x] = src[(size_t)(kb + y + 8 * i) * N + nb + x];
    __syncthreads();
    #pragma unroll
    for (int i = 0; i < 4; i++)
        dst[(size_t)(nb + y + 8 * i) * K + kb + x] = __float2half(t[x][y + 8 * i]);
}

// ---------------- fp16 mma.sync GEMM 128x128, 3-stage cp.async, SINGLE barrier/iter ----------------
// EPI: 2 half bias+gelu | 3 float +res | 4 float bias+res | 5 half none
#define STG_BYTES 32768
#define SMEM_DYN (3 * STG_BYTES)

template<int EPI>
__global__ void __launch_bounds__(256)
hgemm(const __half* __restrict__ A, const __half* __restrict__ Bt, void* __restrict__ Cv,
      int M_, int N_, int K_, const float* __restrict__ bias, const float* __restrict__ res) {
    extern __shared__ char sm[];
    uint32_t sbase = smem_u32(sm);
    int tid = threadIdx.x, wid = tid >> 5, lane = tid & 31;
    int g = lane >> 2, tg = lane & 3;
    int bm = blockIdx.y * 128, bn = blockIdx.x * 128;
    int wm = (wid & 1) * 64, wn = (wid >> 1) * 32;

    int lrow = tid >> 1, lc0 = (tid & 1) * 4;
    const __half* gA = A + (size_t)(bm + lrow) * K_ + lc0 * 8;
    const __half* gB = Bt + (size_t)(bn + lrow) * K_ + lc0 * 8;
    uint32_t sAo[4], sBo[4];
    #pragma unroll
    for (int i = 0; i < 4; i++) {
        uint32_t off = lrow * 128 + (lc0 + i) * 16;
        sAo[i] = SWZ(off);
        sBo[i] = 16384 + SWZ(off);
    }
    auto load_stage = [&](int chunk, int stage) {
        uint32_t st = sbase + stage * STG_BYTES;
        const __half* a = gA + chunk * 64;
        const __half* b = gB + chunk * 64;
        #pragma unroll
        for (int i = 0; i < 4; i++) cpa16(st + sAo[i], a + i * 8);
        #pragma unroll
        for (int i = 0; i < 4; i++) cpa16(st + sBo[i], b + i * 8);
        asm volatile("cp.async.commit_group;" ::: "memory");
    };

    int arow = lane & 15;
    int acb  = (lane >> 4) * 16;
    int bsel = lane >> 3;
    int brow = (lane & 7) + ((bsel & 2) ? 8 : 0);
    int bcb  = (bsel & 1) * 16;
    uint32_t aBase[4], bBase[2];
    #pragma unroll
    for (int mt = 0; mt < 4; mt++)
        aBase[mt] = (wm + mt * 16 + arow) * 128 + acb;
    #pragma unroll
    for (int np = 0; np < 2; np++)
        bBase[np] = 16384 + (wn + np * 16 + brow) * 128 + bcb;

    float acc[4][4][4];
    #pragma unroll
    for (int i = 0; i < 4; i++)
        #pragma unroll
        for (int j = 0; j < 4; j++)
            #pragma unroll
            for (int r = 0; r < 4; r++) acc[i][j][r] = 0.f;

    const int NK = K_ >> 6;
    load_stage(0, 0);
    load_stage(1, 1);

    for (int k = 0; k < NK; k++) {
        int sk = k - (k / 3) * 3;
        asm volatile("cp.async.wait_group %0;" :: "n"(1) : "memory");
        __syncthreads();   // single barrier: everyone done reading stage (k-1)%3 == (k+2)%3

        // issue next loads FIRST (into the stage just retired), then compute
        if (k + 2 < NK) load_stage(k + 2, (k + 2) - ((k + 2) / 3) * 3);
        else asm volatile("cp.async.commit_group;" ::: "memory");

        uint32_t st = sbase + sk * STG_BYTES;
        #pragma unroll
        for (int kk = 0; kk < 4; kk++) {
            int kbyte = kk * 32;
            uint32_t af[4][4], bf[4][2];
            #pragma unroll
            for (int mt = 0; mt < 4; mt++)
                ldm4(af[mt], st + SWZ(aBase[mt] + kbyte));
            #pragma unroll
            for (int np = 0; np < 2; np++) {
                uint32_t r4[4];
                ldm4(r4, st + SWZ(bBase[np] + kbyte));
                bf[2 * np][0] = r4[0]; bf[2 * np][1] = r4[1];
                bf[2 * np + 1][0] = r4[2]; bf[2 * np + 1][1] = r4[3];
            }
            #pragma unroll
            for (int mt = 0; mt < 4; mt++)
                #pragma unroll
                for (int nt = 0; nt < 4; nt++)
                    asm volatile(
                        "mma.sync.aligned.m16n8k16.row.col.f32.f16.f16.f32 "
                        "{%0,%1,%2,%3}, {%4,%5,%6,%7}, {%8,%9}, {%0,%1,%2,%3};"
                        : "+f"(acc[mt][nt][0]), "+f"(acc[mt][nt][1]),
                          "+f"(acc[mt][nt][2]), "+f"(acc[mt][nt][3])
                        : "r"(af[mt][0]), "r"(af[mt][1]), "r"(af[mt][2]), "r"(af[mt][3]),
                          "r"(bf[nt][0]), "r"(bf[nt][1]));
        }
    }

    float* Cf = (float*)Cv;
    __half* Ch = (__half*)Cv;
    #pragma unroll
    for (int mt = 0; mt < 4; mt++) {
        #pragma unroll
        for (int nt = 0; nt < 4; nt++) {
            int col = bn + wn + nt * 8 + 2 * tg;
            float b0 = 0.f, b1 = 0.f;
            if (EPI == 2 || EPI == 4) { b0 = bias[col]; b1 = bias[col + 1]; }
            #pragma unroll
            for (int h2 = 0; h2 < 2; h2++) {
                int row = bm + wm + mt * 16 + g + h2 * 8;
                float v0 = acc[mt][nt][2 * h2], v1 = acc[mt][nt][2 * h2 + 1];
                if (EPI == 2 || EPI == 4) { v0 += b0; v1 += b1; }
                if (EPI == 2 || EPI == 5) {
                    __half2 hv;
                    hv.x = __float2half(EPI == 2 ? geluf_(v0) : v0);
                    hv.y = __float2half(EPI == 2 ? geluf_(v1) : v1);
                    *(__half2*)(Ch + (size_t)row * N_ + col) = hv;
                } else {
                    if (EPI == 3 || EPI == 4) {
                        float2 rr = *(const float2*)(res + (size_t)row * N_ + col);
                        v0 += rr.x; v1 += rr.y;
                    }
                    float2 o2; o2.x = v0; o2.y = v1;
                    *(float2*)(Cf + (size_t)row * N_ + col) = o2;
                }
            }
        }
    }
}

// ---------------- LayerNorm -> half ----------------
__global__ void ln_kernel(const float* __restrict__ x, const float* __restrict__ w,
                          const float* __restrict__ b, __half* __restrict__ out) {
    int row = blockIdx.x;
    const float* xr = x + (size_t)row * Dd;
    float s1 = 0.f, s2 = 0.f;
    float vals[4];
    #pragma unroll
    for (int i = 0; i < 4; i++) {
        float v = xr[threadIdx.x + i * 256];
        vals[i] = v; s1 += v; s2 += v * v;
    }
    __shared__ float sh[2][8];
    int lane = threadIdx.x & 31, wid = threadIdx.x >> 5;
    #pragma unroll
    for (int off = 16; off > 0; off >>= 1) {
        s1 += __shfl_xor_sync(0xffffffffu, s1, off);
        s2 += __shfl_xor_sync(0xffffffffu, s2, off);
    }
    if (lane == 0) { sh[0][wid] = s1; sh[1][wid] = s2; }
    __syncthreads();
    if (threadIdx.x == 0) {
        float a = 0.f, c = 0.f;
        #pragma unroll
        for (int i = 0; i < 8; i++) { a += sh[0][i]; c += sh[1][i]; }
        sh[0][0] = a; sh[1][0] = c;
    }
    __syncthreads();
    float mean = sh[0][0] * (1.0f / Dd);
    float var  = sh[1][0] * (1.0f / Dd) - mean * mean;
    float inv  = rsqrtf(var + 1e-5f);
    #pragma unroll
    for (int i = 0; i < 4; i++) {
        int c = threadIdx.x + i * 256;
        out[(size_t)row * Dd + c] = __float2half((vals[i] - mean) * inv * w[c] + b[c]);
    }
}

// ---------------- g / beta ----------------
__global__ void gbeta_kernel(const __half* __restrict__ normed, const float* __restrict__ Wa,
                             const float* __restrict__ Wb, const float* __restrict__ A_log,
                             const float* __restrict__ dt_bias, float* __restrict__ g,
                             float* __restrict__ beta) {
    int row = blockIdx.x * 8 + (threadIdx.x >> 5);
    int lane = threadIdx.x & 31;
    const __half* xr = normed + (size_t)row * Dd;
    float acc[8];
    #pragma unroll
    for (int j = 0; j < 8; j++) acc[j] = 0.f;
    for (int k = lane; k < Dd; k += 32) {
        float xv = __half2float(xr[k]);
        const float* wa = Wa + k * 4;
        const float* wb = Wb + k * 4;
        #pragma unroll
        for (int j = 0; j < 4; j++) { acc[j] += xv * wa[j]; acc[4 + j] += xv * wb[j]; }
    }
    #pragma unroll
    for (int off = 16; off > 0; off >>= 1)
        #pragma unroll
        for (int j = 0; j < 8; j++) acc[j] += __shfl_xor_sync(0xffffffffu, acc[j], off);
    if (lane < 4) {
        float xa = acc[lane] + dt_bias[lane];
        g[row * 4 + lane] = -expf(A_log[lane]) * softplusf_(xa);
        beta[row * 4 + lane] = sigmoidf_(acc[4 + lane]);
    }
}

// ---------------- fused conv+SiLU+l2norm for q AND k (half2 vectorized) ----------------
__global__ void conv_l2_kernel(const __half* __restrict__ xall,
                               const float* __restrict__ wq, const float* __restrict__ wk,
                               float* __restrict__ qout, float* __restrict__ kout) {
    int bid = blockIdx.x;
    bool isq = bid < NROWS * Hh;
    int rowh = isq ? bid : bid - NROWS * Hh;
    long row = rowh >> 2;
    int h = rowh & 3;
    int t = (int)(row & (Tt - 1));
    long bbase = row - t;
    int c = h * DKk + threadIdx.x * 2;
    int coff = isq ? 0 : 1024;
    const float* w = isq ? wq : wk;
    float wA[2][4] = {{w[c*4+0], w[c*4+1], w[c*4+2], w[c*4+3]},
                      {w[c*4+4], w[c*4+5], w[c*4+6], w[c*4+7]}};
    float a0 = 0.f, a1 = 0.f;
    #pragma unroll
    for (int i = 0; i < 4; i++) {
        int tt = t - 3 + i;
        if (tt >= 0) {
            __half2 hv = *(const __half2*)(xall + (bbase + tt) * (long)NQKVG + coff + c);
            float2 fv = __half22float2(hv);
            a0 += fv.x * wA[0][i];
            a1 += fv.y * wA[1][i];
        }
    }
    float v0 = siluf_(a0), v1 = siluf_(a1);
    float ss = v0 * v0 + v1 * v1;
    __shared__ float sh[4];
    int lane = threadIdx.x & 31, wid = threadIdx.x >> 5;
    #pragma unroll
    for (int off = 16; off > 0; off >>= 1) ss += __shfl_xor_sync(0xffffffffu, ss, off);
    if (lane == 0) sh[wid] = ss;
    __syncthreads();
    if (threadIdx.x == 0) sh[0] = sh[0] + sh[1] + sh[2] + sh[3];
    __syncthreads();
    float sc = (isq ? 0.0625f : 1.0f) * rsqrtf(sh[0] + 1e-6f);
    float* outp = isq ? qout : kout;
    float2 o2; o2.x = v0 * sc; o2.y = v1 * sc;
    *(float2*)(outp + row * KDIM + c) = o2;
}

// ---------------- conv + SiLU for V (half2 vectorized) ----------------
__global__ void conv_silu_kernel(const __half* __restrict__ x, int coff,
                                 const float* __restrict__ w,
                                 float* __restrict__ y, long total2) {
    long idx = (long)blockIdx.x * blockDim.x + threadIdx.x;
    if (idx >= total2) return;
    int c = (int)(idx % (VDIM / 2)) * 2;
    long bt = idx / (VDIM / 2);
    int t = (int)(bt % Tt);
    long bbase = (bt / Tt) * Tt;
    const float* w4 = w + c * 4;
    float a0 = 0.f, a1 = 0.f;
    #pragma unroll
    for (int i = 0; i < 4; i++) {
        int tt = t - 3 + i;
        if (tt >= 0) {
            __half2 hv = *(const __half2*)(x + (bbase + tt) * (long)NQKVG + coff + c);
            float2 fv = __half22float2(hv);
            a0 += fv.x * w4[i];
            a1 += fv.y * w4[4 + i];
        }
    }
    float2 o2; o2.x = siluf_(a0); o2.y = siluf_(a1);
    *(float2*)(y + bt * VDIM + c) = o2;
}

// ---------------- gated delta rule scan: R9-proven (cp.async ring depth 8 + f32x2) ----------------
#define KSTR 68
#define RD 8
__global__ void __launch_bounds__(256)
scan_kernel(const float* __restrict__ q, const float* __restrict__ k, const float* __restrict__ v,
            const float* __restrict__ g, const float* __restrict__ beta, float* __restrict__ o) {
    int b  = blockIdx.x >> 5;
    int h  = (blockIdx.x >> 3) & 3;
    int sl = blockIdx.x & 7;
    int v0 = sl * 64;
    int tid = threadIdx.x;
    int kb = tid & 3, vi = tid >> 2;
    int kb68 = kb * KSTR;

    __shared__ float qs[RD][4 * KSTR], ks[RD][4 * KSTR], vs[RD][64], sgb[RD][2];

    const float* qp = q + (size_t)b * Tt * KDIM + h * DKk + tid;
    const float* kp = k + (size_t)b * Tt * KDIM + h * DKk + tid;
    const float* vp = v + (size_t)b * Tt * VDIM + h * DVv + v0 + tid;
    const float* gp = g + (size_t)b * Tt * Hh + h;
    const float* bp = beta + (size_t)b * Tt * Hh + h;

    uint32_t qdst0 = smem_u32(&qs[0][kb * KSTR + vi]);
    uint32_t kdst0 = smem_u32(&ks[0][kb * KSTR + vi]);
    uint32_t vdst0 = smem_u32(&vs[0][tid & 63]);
    uint32_t gdst0 = smem_u32(&sgb[0][0]);
    const uint32_t QKROW = 4 * KSTR * 4;

    auto prefetch = [&](int t) {
        int st = t & (RD - 1);
        cpa4(qdst0 + st * QKROW, qp + (size_t)t * KDIM);
        cpa4(kdst0 + st * QKROW, kp + (size_t)t * KDIM);
        if (tid < 64)       cpa4(vdst0 + st * 256, vp + (size_t)t * VDIM);
        else if (tid == 64) cpa4(gdst0 + st * 8,     gp + (size_t)t * Hh);
        else if (tid == 65) cpa4(gdst0 + st * 8 + 4, bp + (size_t)t * Hh);
    };

    #pragma unroll
    for (int t = 0; t < RD - 1; t++) {
        prefetch(t);
        asm volatile("cp.async.commit_group;" ::: "memory");
    }

    u64t S2[32];
    #pragma unroll
    for (int j = 0; j < 32; j++) S2[j] = 0ull;
    u64t kreg2[32];

    for (int t = 0; t < Tt; t++) {
        asm volatile("cp.async.wait_group %0;" :: "n"(RD - 2) : "memory");
        __syncthreads();
        int st = t & (RD - 1);

        int tp = t + RD - 1;
        if (tp < Tt) prefetch(tp);
        asm volatile("cp.async.commit_group;" ::: "memory");

        float eg = expf(sgb[st][0]);
        float bt = sgb[st][1];
        u64t eg2; PACK2(eg2, eg, eg);

        u64t p2a = 0ull, p2b = 0ull;
        #pragma unroll
        for (int jj = 0; jj < 16; jj++) {
            ulonglong2 kv = *(const ulonglong2*)&ks[st][kb68 + 4 * jj];
            kreg2[2 * jj]     = kv.x;
            kreg2[2 * jj + 1] = kv.y;
            FMA2(p2a, kv.x, S2[2 * jj],     p2a);
            FMA2(p2b, kv.y, S2[2 * jj + 1], p2b);
        }
        ADD2(p2a, p2a, p2b);
        float plo, phi;
        UNPK2(plo, phi, p2a);
        float partial = plo + phi;
        partial += __shfl_xor_sync(0xffffffffu, partial, 1);
        partial += __shfl_xor_sync(0xffffffffu, partial, 2);
        float delta = (vs[st][vi] - eg * partial) * bt;
        u64t d2; PACK2(d2, delta, delta);

        u64t o2a = 0ull, o2b = 0ull;
        #pragma unroll
        for (int jj = 0; jj < 16; jj++) {
            ulonglong2 qv = *(const ulonglong2*)&qs[st][kb68 + 4 * jj];
            u64t t0, t1;
            MUL2(t0, kreg2[2 * jj],     d2);
            MUL2(t1, kreg2[2 * jj + 1], d2);
            FMA2(S2[2 * jj],     eg2, S2[2 * jj],     t0);
            FMA2(S2[2 * jj + 1], eg2, S2[2 * jj + 1], t1);
            FMA2(o2a, qv.x, S2[2 * jj],     o2a);
            FMA2(o2b, qv.y, S2[2 * jj + 1], o2b);
        }
        ADD2(o2a, o2a, o2b);
        float olo, ohi;
        UNPK2(olo, ohi, o2a);
        float opart = olo + ohi;
        opart += __shfl_xor_sync(0xffffffffu, opart, 1);
        opart += __shfl_xor_sync(0xffffffffu, opart, 2);
        if (kb == 0) o[((size_t)b * Tt + t) * VDIM + h * DVv + v0 + vi] = opart;
    }
}

// ---------------- gated RMSNorm + silu(gate) -> half ----------------
__global__ void rmsgate_kernel(const float* __restrict__ o, const __half* __restrict__ xall,
                               const float* __restrict__ onw, __half* __restrict__ oh) {
    int rowh = blockIdx.x;
    long row = rowh >> 2;
    int h = rowh & 3;
    const float* op = o + row * VDIM + h * DVv;
    const __half* gp = xall + row * (long)NQKVG + 4096 + h * DVv;
    __half* ohp = oh + row * VDIM + h * DVv;
    float v1 = op[threadIdx.x], v2 = op[threadIdx.x + 256];
    float ss = v1 * v1 + v2 * v2;
    __shared__ float sh[8];
    int lane = threadIdx.x & 31, wid = threadIdx.x >> 5;
    #pragma unroll
    for (int off = 16; off > 0; off >>= 1) ss += __shfl_xor_sync(0xffffffffu, ss, off);
    if (lane == 0) sh[wid] = ss;
    __syncthreads();
    if (threadIdx.x == 0) {
        float a = 0.f;
        #pragma unroll
        for (int i = 0; i < 8; i++) a += sh[i];
        sh[0] = a;
    }
    __syncthreads();
    float scale = rsqrtf(sh[0] * (1.0f / DVv) + 1e-5f);
    int c1 = threadIdx.x, c2 = threadIdx.x + 256;
    ohp[c1] = __float2half(v1 * scale * onw[c1] * siluf_(__half2float(gp[c1])));
    ohp[c2] = __float2half(v2 * scale * onw[c2] * siluf_(__half2float(gp[c2])));
}

// ---------------- launcher ----------------
extern "C" void kernel_launch(void* const* d_in, const int* in_sizes, int n_in,
                              void* d_out, int out_size) {
    const float* x        = (const float*)d_in[0];
    const float* Wq       = (const float*)d_in[1];
    const float* Wk       = (const float*)d_in[2];
    const float* Wv       = (const float*)d_in[3];
    const float* Wa       = (const float*)d_in[4];
    const float* Wb       = (const float*)d_in[5];
    const float* Wg       = (const float*)d_in[6];
    const float* conv_q_w = (const float*)d_in[7];
    const float* conv_k_w = (const float*)d_in[8];
    const float* conv_v_w = (const float*)d_in[9];
    const float* A_log    = (const float*)d_in[10];
    const float* dt_bias  = (const float*)d_in[11];
    const float* o_norm_w = (const float*)d_in[12];
    const float* Wo       = (const float*)d_in[13];
    const float* ln1_w    = (const float*)d_in[14];
    const float* ln1_b    = (const float*)d_in[15];
    const float* ln2_w    = (const float*)d_in[16];
    const float* ln2_b    = (const float*)d_in[17];
    const float* ffn_w1   = (const float*)d_in[18];
    const float* ffn_b1   = (const float*)d_in[19];
    const float* ffn_w2   = (const float*)d_in[20];
    const float* ffn_b2   = (const float*)d_in[21];
    float* out = (float*)d_out;

    __half *normh, *xallh, *oh, *hbufh, *ffn1h, *wth;
    float *q, *k, *v, *gg, *bb, *o, *x2;
    cudaGetSymbolAddress((void**)&normh, g_normh);
    cudaGetSymbolAddress((void**)&xallh, g_xallh);
    cudaGetSymbolAddress((void**)&q, g_q);
    cudaGetSymbolAddress((void**)&k, g_k);
    cudaGetSymbolAddress((void**)&v, g_v);
    cudaGetSymbolAddress((void**)&gg, g_gg);
    cudaGetSymbolAddress((void**)&bb, g_bb);
    cudaGetSymbolAddress((void**)&o, g_o);
    cudaGetSymbolAddress((void**)&oh, g_oh);
    cudaGetSymbolAddress((void**)&x2, g_x2);
    cudaGetSymbolAddress((void**)&hbufh, g_hbufh);
    cudaGetSymbolAddress((void**)&ffn1h, g_ffn1h);
    cudaGetSymbolAddress((void**)&wth, g_wth);

    cudaFuncSetAttribute(hgemm<2>, cudaFuncAttributeMaxDynamicSharedMemorySize, SMEM_DYN);
    cudaFuncSetAttribute(hgemm<3>, cudaFuncAttributeMaxDynamicSharedMemorySize, SMEM_DYN);
    cudaFuncSetAttribute(hgemm<4>, cudaFuncAttributeMaxDynamicSharedMemorySize, SMEM_DYN);
    cudaFuncSetAttribute(hgemm<5>, cudaFuncAttributeMaxDynamicSharedMemorySize, SMEM_DYN);

    // 0: all weight transposes
    transpose_all_kernel<<<16384, dim3(32, 8)>>>(Wq, Wk, Wv, Wg, Wo, ffn_w1, ffn_w2, wth);

    // 1: LN1 -> half
    ln_kernel<<<NROWS, 256>>>(x, ln1_w, ln1_b, normh);

    // 2: g/beta
    gbeta_kernel<<<NROWS / 8, 256>>>(normh, Wa, Wb, A_log, dt_bias, gg, bb);

    // 3: fused Q|K|V|G projection -> half (ncu capture lands here)
    hgemm<5><<<dim3(NQKVG/128, NROWS/128), 256, SMEM_DYN>>>(normh, wth + WT_QKVG, xallh,
                                                            NROWS, NQKVG, Dd, nullptr, nullptr);

    // 4: conv + silu + l2norm for q and k
    conv_l2_kernel<<<NROWS * Hh * 2, 128>>>(xallh, conv_q_w, conv_k_w, q, k);
    // 5: conv + silu for v
    {
        long tv2 = (long)NROWS * (VDIM / 2);
        conv_silu_kernel<<<(unsigned)((tv2 + 255) / 256), 256>>>(xallh, 2048, conv_v_w, v, tv2);
    }

    // 6: scan (R9-proven)
    scan_kernel<<<Bb * Hh * 8, 256>>>(q, k, v, gg, bb, o);

    // 7: gated RMSNorm -> half
    rmsgate_kernel<<<NROWS * Hh, 256>>>(o, xallh, o_norm_w, oh);

    // 8: x2 = x + oh @ WoT
    hgemm<3><<<dim3(Dd/128, NROWS/128), 256, SMEM_DYN>>>(oh, wth + WT_O, x2,
                                                         NROWS, Dd, VDIM, nullptr, x);

    // 9: LN2 + FFN
    ln_kernel<<<NROWS, 256>>>(x2, ln2_w, ln2_b, hbufh);
    hgemm<2><<<dim3(FFND/128, NROWS/128), 256, SMEM_DYN>>>(hbufh, wth + WT_F1, ffn1h,
                                                           NROWS, FFND, Dd, ffn_b1, nullptr);
    hgemm<4><<<dim3(Dd/128, NROWS/128), 256, SMEM_DYN>>>(ffn1h, wth + WT_F2, out,
                                                         NROWS, Dd, FFND, ffn_b2, x2);
}

// round 15
// speedup vs baseline: 1.1109x; 1.0691x over previous
#include <cuda_runtime.h>
#include <cuda_fp16.h>
#include <math.h>
#include <stdint.h>

#define Bb   4
#define Tt   2048
#define Dd   1024
#define Hh   4
#define DKk  256
#define DVv  512
#define KDIM 1024
#define VDIM 2048
#define FFND 4096
#define NROWS (Bb*Tt)   /* 8192 */
#define NQKVG 6144

// ---------------- scratch ----------------
__device__ __half  g_normh[NROWS*Dd];
__device__ __half  g_xallh[(size_t)NROWS*NQKVG];
__device__ float   g_q[NROWS*KDIM];
__device__ float   g_k[NROWS*KDIM];
__device__ float   g_v[NROWS*VDIM];
__device__ float   g_gg[NROWS*Hh];     /* holds exp(g) */
__device__ float   g_bb[NROWS*Hh];
__device__ float   g_o[NROWS*VDIM];
__device__ __half  g_oh[NROWS*VDIM];
__device__ float   g_x2[NROWS*Dd];
__device__ __half  g_hbufh[NROWS*Dd];
__device__ __half  g_ffn1h[(size_t)NROWS*FFND];
__device__ __half  g_wth[16*1024*1024];
#define WT_QKVG 0
#define WT_O   (6*1024*1024)
#define WT_F1  (8*1024*1024)
#define WT_F2  (12*1024*1024)

// ---------------- helpers ----------------
__device__ __forceinline__ float sigmoidf_(float x) { return 1.0f / (1.0f + expf(-x)); }
__device__ __forceinline__ float siluf_(float x)    { return x * sigmoidf_(x); }
__device__ __forceinline__ float geluf_(float x)    { return 0.5f * x * (1.0f + erff(x * 0.70710678118654752f)); }
__device__ __forceinline__ float softplusf_(float x){ return (x > 20.0f) ? x : log1pf(expf(x)); }
__device__ __forceinline__ uint32_t smem_u32(const void* p) {
    uint32_t a;
    asm("{ .reg .u64 t; cvta.to.shared.u64 t, %1; cvt.u32.u64 %0, t; }" : "=r"(a) : "l"(p));
    return a;
}
__device__ __forceinline__ void cpa16(uint32_t dst, const void* src) {
    asm volatile("cp.async.cg.shared.global [%0], [%1], 16;" :: "r"(dst), "l"(src));
}
__device__ __forceinline__ void cpa4(uint32_t dst, const void* src) {
    asm volatile("cp.async.ca.shared.global [%0], [%1], 4;" :: "r"(dst), "l"(src));
}
__device__ __forceinline__ void ldm4(uint32_t* r, uint32_t addr) {
    asm volatile("ldmatrix.sync.aligned.m8n8.x4.shared.b16 {%0,%1,%2,%3}, [%4];"
        : "=r"(r[0]), "=r"(r[1]), "=r"(r[2]), "=r"(r[3]) : "r"(addr));
}
#define SWZ(o) ((o) ^ (((o) >> 3) & 0x70))

typedef unsigned long long u64t;
#define FMA2(d, a, b, c) asm("fma.rn.f32x2 %0, %1, %2, %3;" : "=l"(d) : "l"(a), "l"(b), "l"(c))
#define MUL2(d, a, b)    asm("mul.rn.f32x2 %0, %1, %2;"     : "=l"(d) : "l"(a), "l"(b))
#define ADD2(d, a, b)    asm("add.rn.f32x2 %0, %1, %2;"     : "=l"(d) : "l"(a), "l"(b))
#define PACK2(d, lo, hi) asm("mov.b64 %0, {%1, %2};" : "=l"(d) : "f"(lo), "f"(hi))
#define UNPK2(lo, hi, s) asm("mov.b64 {%0, %1}, %2;" : "=f"(lo), "=f"(hi) : "l"(s))

// ---------------- ONE fused transpose launch: 7 matrices, src[K,N] -> half dst[N,K] ----------------
__global__ void transpose_all_kernel(const float* __restrict__ Wq, const float* __restrict__ Wk,
                                     const float* __restrict__ Wv, const float* __restrict__ Wg,
                                     const float* __restrict__ Wo, const float* __restrict__ F1,
                                     const float* __restrict__ F2, __half* __restrict__ wth) {
    const int cum[7] = {1024, 2048, 4096, 6144, 8192, 12288, 16384};
    const int Ks[7]  = {1024, 1024, 1024, 1024, 2048, 1024, 4096};
    const int Ns[7]  = {1024, 1024, 2048, 2048, 1024, 4096, 1024};
    const size_t doff[7] = {0, 1024*1024, 2*1024*1024, 4*1024*1024,
                            6*1024*1024, 8*1024*1024, 12*1024*1024};
    int bid = blockIdx.x;
    int m = 0;
    #pragma unroll
    for (int i = 0; i < 7; i++) if (bid >= cum[i]) m = i + 1;
    int lt = bid - (m ? cum[m - 1] : 0);
    const float* srcs[7] = {Wq, Wk, Wv, Wg, Wo, F1, F2};
    const float* src = srcs[m];
    __half* dst = wth + doff[m];
    int K = Ks[m], N = Ns[m];
    int tilesN = N >> 5;
    int nb = (lt % tilesN) * 32, kb = (lt / tilesN) * 32;

    __shared__ float t[32][33];
    int x = threadIdx.x, y = threadIdx.y;
    #pragma unroll
    for (int i = 0; i < 4; i++)
        t[y + 8 * i][x] = src[(size_t)(kb + y + 8 * i) * N + nb + x];
    __syncthreads();
    #pragma unroll
    for (int i = 0; i < 4; i++)
        dst[(size_t)(nb + y + 8 * i) * K + kb + x] = __float2half(t[x][y + 8 * i]);
}

// ---------------- fp16 mma.sync GEMM 128x128, 3-stage cp.async, single barrier/iter ----------------
// EPI: 2 half bias+gelu | 3 float +res | 4 float bias+res | 5 half none
#define STG_BYTES 32768
#define SMEM_DYN (3 * STG_BYTES)

template<int EPI>
__global__ void __launch_bounds__(256)
hgemm(const __half* __restrict__ A, const __half* __restrict__ Bt, void* __restrict__ Cv,
      int M_, int N_, int K_, const float* __restrict__ bias, const float* __restrict__ res) {
    extern __shared__ char sm[];
    uint32_t sbase = smem_u32(sm);
    int tid = threadIdx.x, wid = tid >> 5, lane = tid & 31;
    int g = lane >> 2, tg = lane & 3;
    int bm = blockIdx.y * 128, bn = blockIdx.x * 128;
    int wm = (wid & 1) * 64, wn = (wid >> 1) * 32;

    int lrow = tid >> 1, lc0 = (tid & 1) * 4;
    const __half* gA = A + (size_t)(bm + lrow) * K_ + lc0 * 8;
    const __half* gB = Bt + (size_t)(bn + lrow) * K_ + lc0 * 8;
    uint32_t sAo[4], sBo[4];
    #pragma unroll
    for (int i = 0; i < 4; i++) {
        uint32_t off = lrow * 128 + (lc0 + i) * 16;
        sAo[i] = SWZ(off);
        sBo[i] = 16384 + SWZ(off);
    }
    auto load_stage = [&](int chunk, int stage) {
        uint32_t st = sbase + stage * STG_BYTES;
        const __half* a = gA + chunk * 64;
        const __half* b = gB + chunk * 64;
        #pragma unroll
        for (int i = 0; i < 4; i++) cpa16(st + sAo[i], a + i * 8);
        #pragma unroll
        for (int i = 0; i < 4; i++) cpa16(st + sBo[i], b + i * 8);
        asm volatile("cp.async.commit_group;" ::: "memory");
    };

    int arow = lane & 15;
    int acb  = (lane >> 4) * 16;
    int bsel = lane >> 3;
    int brow = (lane & 7) + ((bsel & 2) ? 8 : 0);
    int bcb  = (bsel & 1) * 16;
    uint32_t aBase[4], bBase[2];
    #pragma unroll
    for (int mt = 0; mt < 4; mt++)
        aBase[mt] = (wm + mt * 16 + arow) * 128 + acb;
    #pragma unroll
    for (int np = 0; np < 2; np++)
        bBase[np] = 16384 + (wn + np * 16 + brow) * 128 + bcb;

    float acc[4][4][4];
    #pragma unroll
    for (int i = 0; i < 4; i++)
        #pragma unroll
        for (int j = 0; j < 4; j++)
            #pragma unroll
            for (int r = 0; r < 4; r++) acc[i][j][r] = 0.f;

    const int NK = K_ >> 6;
    load_stage(0, 0);
    load_stage(1, 1);

    for (int k = 0; k < NK; k++) {
        int sk = k - (k / 3) * 3;
        asm volatile("cp.async.wait_group %0;" :: "n"(1) : "memory");
        __syncthreads();

        if (k + 2 < NK) load_stage(k + 2, (k + 2) - ((k + 2) / 3) * 3);
        else asm volatile("cp.async.commit_group;" ::: "memory");

        uint32_t st = sbase + sk * STG_BYTES;
        #pragma unroll
        for (int kk = 0; kk < 4; kk++) {
            int kbyte = kk * 32;
            uint32_t af[4][4], bf[4][2];
            #pragma unroll
            for (int mt = 0; mt < 4; mt++)
                ldm4(af[mt], st + SWZ(aBase[mt] + kbyte));
            #pragma unroll
            for (int np = 0; np < 2; np++) {
                uint32_t r4[4];
                ldm4(r4, st + SWZ(bBase[np] + kbyte));
                bf[2 * np][0] = r4[0]; bf[2 * np][1] = r4[1];
                bf[2 * np + 1][0] = r4[2]; bf[2 * np + 1][1] = r4[3];
            }
            #pragma unroll
            for (int mt = 0; mt < 4; mt++)
                #pragma unroll
                for (int nt = 0; nt < 4; nt++)
                    asm volatile(
                        "mma.sync.aligned.m16n8k16.row.col.f32.f16.f16.f32 "
                        "{%0,%1,%2,%3}, {%4,%5,%6,%7}, {%8,%9}, {%0,%1,%2,%3};"
                        : "+f"(acc[mt][nt][0]), "+f"(acc[mt][nt][1]),
                          "+f"(acc[mt][nt][2]), "+f"(acc[mt][nt][3])
                        : "r"(af[mt][0]), "r"(af[mt][1]), "r"(af[mt][2]), "r"(af[mt][3]),
                          "r"(bf[nt][0]), "r"(bf[nt][1]));
        }
    }

    float* Cf = (float*)Cv;
    __half* Ch = (__half*)Cv;
    #pragma unroll
    for (int mt = 0; mt < 4; mt++) {
        #pragma unroll
        for (int nt = 0; nt < 4; nt++) {
            int col = bn + wn + nt * 8 + 2 * tg;
            float b0 = 0.f, b1 = 0.f;
            if (EPI == 2 || EPI == 4) { b0 = bias[col]; b1 = bias[col + 1]; }
            #pragma unroll
            for (int h2 = 0; h2 < 2; h2++) {
                int row = bm + wm + mt * 16 + g + h2 * 8;
                float v0 = acc[mt][nt][2 * h2], v1 = acc[mt][nt][2 * h2 + 1];
                if (EPI == 2 || EPI == 4) { v0 += b0; v1 += b1; }
                if (EPI == 2 || EPI == 5) {
                    __half2 hv;
                    hv.x = __float2half(EPI == 2 ? geluf_(v0) : v0);
                    hv.y = __float2half(EPI == 2 ? geluf_(v1) : v1);
                    *(__half2*)(Ch + (size_t)row * N_ + col) = hv;
                } else {
                    if (EPI == 3 || EPI == 4) {
                        float2 rr = *(const float2*)(res + (size_t)row * N_ + col);
                        v0 += rr.x; v1 += rr.y;
                    }
                    float2 o2; o2.x = v0; o2.y = v1;
                    *(float2*)(Cf + (size_t)row * N_ + col) = o2;
                }
            }
        }
    }
}

// ---------------- LayerNorm -> half ----------------
__global__ void ln_kernel(const float* __restrict__ x, const float* __restrict__ w,
                          const float* __restrict__ b, __half* __restrict__ out) {
    int row = blockIdx.x;
    const float* xr = x + (size_t)row * Dd;
    float s1 = 0.f, s2 = 0.f;
    float vals[4];
    #pragma unroll
    for (int i = 0; i < 4; i++) {
        float v = xr[threadIdx.x + i * 256];
        vals[i] = v; s1 += v; s2 += v * v;
    }
    __shared__ float sh[2][8];
    int lane = threadIdx.x & 31, wid = threadIdx.x >> 5;
    #pragma unroll
    for (int off = 16; off > 0; off >>= 1) {
        s1 += __shfl_xor_sync(0xffffffffu, s1, off);
        s2 += __shfl_xor_sync(0xffffffffu, s2, off);
    }
    if (lane == 0) { sh[0][wid] = s1; sh[1][wid] = s2; }
    __syncthreads();
    if (threadIdx.x == 0) {
        float a = 0.f, c = 0.f;
        #pragma unroll
        for (int i = 0; i < 8; i++) { a += sh[0][i]; c += sh[1][i]; }
        sh[0][0] = a; sh[1][0] = c;
    }
    __syncthreads();
    float mean = sh[0][0] * (1.0f / Dd);
    float var  = sh[1][0] * (1.0f / Dd) - mean * mean;
    float inv  = rsqrtf(var + 1e-5f);
    #pragma unroll
    for (int i = 0; i < 4; i++) {
        int c = threadIdx.x + i * 256;
        out[(size_t)row * Dd + c] = __float2half((vals[i] - mean) * inv * w[c] + b[c]);
    }
}

// ---------------- g / beta : stores exp(g) directly ----------------
__global__ void gbeta_kernel(const __half* __restrict__ normed, const float* __restrict__ Wa,
                             const float* __restrict__ Wb, const float* __restrict__ A_log,
                             const float* __restrict__ dt_bias, float* __restrict__ eg,
                             float* __restrict__ beta) {
    int row = blockIdx.x * 8 + (threadIdx.x >> 5);
    int lane = threadIdx.x & 31;
    const __half* xr = normed + (size_t)row * Dd;
    float acc[8];
    #pragma unroll
    for (int j = 0; j < 8; j++) acc[j] = 0.f;
    for (int k = lane; k < Dd; k += 32) {
        float xv = __half2float(xr[k]);
        const float* wa = Wa + k * 4;
        const float* wb = Wb + k * 4;
        #pragma unroll
        for (int j = 0; j < 4; j++) { acc[j] += xv * wa[j]; acc[4 + j] += xv * wb[j]; }
    }
    #pragma unroll
    for (int off = 16; off > 0; off >>= 1)
        #pragma unroll
        for (int j = 0; j < 8; j++) acc[j] += __shfl_xor_sync(0xffffffffu, acc[j], off);
    if (lane < 4) {
        float xa = acc[lane] + dt_bias[lane];
        float gval = -expf(A_log[lane]) * softplusf_(xa);
        eg[row * 4 + lane] = expf(gval);
        beta[row * 4 + lane] = sigmoidf_(acc[4 + lane]);
    }
}

// ---------------- fused conv+SiLU+l2norm for q AND k (half2 vectorized) ----------------
__global__ void conv_l2_kernel(const __half* __restrict__ xall,
                               const float* __restrict__ wq, const float* __restrict__ wk,
                               float* __restrict__ qout, float* __restrict__ kout) {
    int bid = blockIdx.x;
    bool isq = bid < NROWS * Hh;
    int rowh = isq ? bid : bid - NROWS * Hh;
    long row = rowh >> 2;
    int h = rowh & 3;
    int t = (int)(row & (Tt - 1));
    long bbase = row - t;
    int c = h * DKk + threadIdx.x * 2;
    int coff = isq ? 0 : 1024;
    const float* w = isq ? wq : wk;
    float wA[2][4] = {{w[c*4+0], w[c*4+1], w[c*4+2], w[c*4+3]},
                      {w[c*4+4], w[c*4+5], w[c*4+6], w[c*4+7]}};
    float a0 = 0.f, a1 = 0.f;
    #pragma unroll
    for (int i = 0; i < 4; i++) {
        int tt = t - 3 + i;
        if (tt >= 0) {
            __half2 hv = *(const __half2*)(xall + (bbase + tt) * (long)NQKVG + coff + c);
            float2 fv = __half22float2(hv);
            a0 += fv.x * wA[0][i];
            a1 += fv.y * wA[1][i];
        }
    }
    float v0 = siluf_(a0), v1 = siluf_(a1);
    float ss = v0 * v0 + v1 * v1;
    __shared__ float sh[4];
    int lane = threadIdx.x & 31, wid = threadIdx.x >> 5;
    #pragma unroll
    for (int off = 16; off > 0; off >>= 1) ss += __shfl_xor_sync(0xffffffffu, ss, off);
    if (lane == 0) sh[wid] = ss;
    __syncthreads();
    if (threadIdx.x == 0) sh[0] = sh[0] + sh[1] + sh[2] + sh[3];
    __syncthreads();
    float sc = (isq ? 0.0625f : 1.0f) * rsqrtf(sh[0] + 1e-6f);
    float* outp = isq ? qout : kout;
    float2 o2; o2.x = v0 * sc; o2.y = v1 * sc;
    *(float2*)(outp + row * KDIM + c) = o2;
}

// ---------------- conv + SiLU for V (half2 vectorized) ----------------
__global__ void conv_silu_kernel(const __half* __restrict__ x, int coff,
                                 const float* __restrict__ w,
                                 float* __restrict__ y, long total2) {
    long idx = (long)blockIdx.x * blockDim.x + threadIdx.x;
    if (idx >= total2) return;
    int c = (int)(idx % (VDIM / 2)) * 2;
    long bt = idx / (VDIM / 2);
    int t = (int)(bt % Tt);
    long bbase = (bt / Tt) * Tt;
    const float* w4 = w + c * 4;
    float a0 = 0.f, a1 = 0.f;
    #pragma unroll
    for (int i = 0; i < 4; i++) {
        int tt = t - 3 + i;
        if (tt >= 0) {
            __half2 hv = *(const __half2*)(x + (bbase + tt) * (long)NQKVG + coff + c);
            float2 fv = __half22float2(hv);
            a0 += fv.x * w4[i];
            a1 += fv.y * w4[4 + i];
        }
    }
    float2 o2; o2.x = siluf_(a0); o2.y = siluf_(a1);
    *(float2*)(y + bt * VDIM + c) = o2;
}

// ---------------- gated delta rule scan: ring depth 8, UNROLL-2 (one barrier per 2 steps) ----------------
#define KSTR 68
#define RD 8
__global__ void __launch_bounds__(256)
scan_kernel(const float* __restrict__ q, const float* __restrict__ k, const float* __restrict__ v,
            const float* __restrict__ egp_, const float* __restrict__ beta, float* __restrict__ o) {
    int b  = blockIdx.x >> 5;
    int h  = (blockIdx.x >> 3) & 3;
    int sl = blockIdx.x & 7;
    int v0 = sl * 64;
    int tid = threadIdx.x;
    int kb = tid & 3, vi = tid >> 2;
    int kb68 = kb * KSTR;

    __shared__ float qs[RD][4 * KSTR], ks[RD][4 * KSTR], vs[RD][64], sgb[RD][2];

    const float* qp = q + (size_t)b * Tt * KDIM + h * DKk + tid;
    const float* kp = k + (size_t)b * Tt * KDIM + h * DKk + tid;
    const float* vp = v + (size_t)b * Tt * VDIM + h * DVv + v0 + tid;
    const float* gp = egp_ + (size_t)b * Tt * Hh + h;
    const float* bp = beta + (size_t)b * Tt * Hh + h;

    uint32_t qdst0 = smem_u32(&qs[0][kb * KSTR + vi]);
    uint32_t kdst0 = smem_u32(&ks[0][kb * KSTR + vi]);
    uint32_t vdst0 = smem_u32(&vs[0][tid & 63]);
    uint32_t gdst0 = smem_u32(&sgb[0][0]);
    const uint32_t QKROW = 4 * KSTR * 4;

    auto prefetch = [&](int t) {
        int st = t & (RD - 1);
        cpa4(qdst0 + st * QKROW, qp + (size_t)t * KDIM);
        cpa4(kdst0 + st * QKROW, kp + (size_t)t * KDIM);
        if (tid < 64)       cpa4(vdst0 + st * 256, vp + (size_t)t * VDIM);
        else if (tid == 64) cpa4(gdst0 + st * 8,     gp + (size_t)t * Hh);
        else if (tid == 65) cpa4(gdst0 + st * 8 + 4, bp + (size_t)t * Hh);
    };

    // prologue: steps 0..5 in 3 paired groups
    #pragma unroll
    for (int i = 0; i < 3; i++) {
        prefetch(2 * i);
        prefetch(2 * i + 1);
        asm volatile("cp.async.commit_group;" ::: "memory");
    }

    u64t S2[32];
    #pragma unroll
    for (int j = 0; j < 32; j++) S2[j] = 0ull;
    u64t kreg2[32];

    float* obase = o + (size_t)b * Tt * VDIM + h * DVv + v0 + vi;

    for (int t = 0; t < Tt; t += 2) {
        // groups complete through steps t+1 (and beyond); slots t+4..t+7 may be in flight
        asm volatile("cp.async.wait_group %0;" :: "n"(2) : "memory");
        __syncthreads();

        // refill slots (t+6)&7, (t+7)&7 — their readers (steps t-2, t-1) finished last iter
        if (t + 6 < Tt) prefetch(t + 6);
        if (t + 7 < Tt) prefetch(t + 7);
        asm volatile("cp.async.commit_group;" ::: "memory");

        #pragma unroll
        for (int u = 0; u < 2; u++) {
            int tc = t + u;
            int st = tc & (RD - 1);

            float eg = sgb[st][0];
            float bt = sgb[st][1];
            u64t eg2; PACK2(eg2, eg, eg);

            u64t p2a = 0ull, p2b = 0ull;
            #pragma unroll
            for (int jj = 0; jj < 16; jj++) {
                ulonglong2 kv = *(const ulonglong2*)&ks[st][kb68 + 4 * jj];
                kreg2[2 * jj]     = kv.x;
                kreg2[2 * jj + 1] = kv.y;
                FMA2(p2a, kv.x, S2[2 * jj],     p2a);
                FMA2(p2b, kv.y, S2[2 * jj + 1], p2b);
            }
            ADD2(p2a, p2a, p2b);
            float plo, phi;
            UNPK2(plo, phi, p2a);
            float partial = plo + phi;
            partial += __shfl_xor_sync(0xffffffffu, partial, 1);
            partial += __shfl_xor_sync(0xffffffffu, partial, 2);
            float delta = (vs[st][vi] - eg * partial) * bt;
            u64t d2; PACK2(d2, delta, delta);

            u64t o2a = 0ull, o2b = 0ull;
            #pragma unroll
            for (int jj = 0; jj < 16; jj++) {
                ulonglong2 qv = *(const ulonglong2*)&qs[st][kb68 + 4 * jj];
                u64t t0, t1;
                MUL2(t0, kreg2[2 * jj],     d2);
                MUL2(t1, kreg2[2 * jj + 1], d2);
                FMA2(S2[2 * jj],     eg2, S2[2 * jj],     t0);
                FMA2(S2[2 * jj + 1], eg2, S2[2 * jj + 1], t1);
                FMA2(o2a, qv.x, S2[2 * jj],     o2a);
                FMA2(o2b, qv.y, S2[2 * jj + 1], o2b);
            }
            ADD2(o2a, o2a, o2b);
            float olo, ohi;
            UNPK2(olo, ohi, o2a);
            float opart = olo + ohi;
            opart += __shfl_xor_sync(0xffffffffu, opart, 1);
            opart += __shfl_xor_sync(0xffffffffu, opart, 2);
            if (kb == 0) obase[(size_t)tc * VDIM] = opart;
        }
    }
}

// ---------------- gated RMSNorm + silu(gate) -> half ----------------
__global__ void rmsgate_kernel(const float* __restrict__ o, const __half* __restrict__ xall,
                               const float* __restrict__ onw, __half* __restrict__ oh) {
    int rowh = blockIdx.x;
    long row = rowh >> 2;
    int h = rowh & 3;
    const float* op = o + row * VDIM + h * DVv;
    const __half* gp = xall + row * (long)NQKVG + 4096 + h * DVv;
    __half* ohp = oh + row * VDIM + h * DVv;
    float v1 = op[threadIdx.x], v2 = op[threadIdx.x + 256];
    float ss = v1 * v1 + v2 * v2;
    __shared__ float sh[8];
    int lane = threadIdx.x & 31, wid = threadIdx.x >> 5;
    #pragma unroll
    for (int off = 16; off > 0; off >>= 1) ss += __shfl_xor_sync(0xffffffffu, ss, off);
    if (lane == 0) sh[wid] = ss;
    __syncthreads();
    if (threadIdx.x == 0) {
        float a = 0.f;
        #pragma unroll
        for (int i = 0; i < 8; i++) a += sh[i];
        sh[0] = a;
    }
    __syncthreads();
    float scale = rsqrtf(sh[0] * (1.0f / DVv) + 1e-5f);
    int c1 = threadIdx.x, c2 = threadIdx.x + 256;
    ohp[c1] = __float2half(v1 * scale * onw[c1] * siluf_(__half2float(gp[c1])));
    ohp[c2] = __float2half(v2 * scale * onw[c2] * siluf_(__half2float(gp[c2])));
}

// ---------------- launcher ----------------
extern "C" void kernel_launch(void* const* d_in, const int* in_sizes, int n_in,
                              void* d_out, int out_size) {
    const float* x        = (const float*)d_in[0];
    const float* Wq       = (const float*)d_in[1];
    const float* Wk       = (const float*)d_in[2];
    const float* Wv       = (const float*)d_in[3];
    const float* Wa       = (const float*)d_in[4];
    const float* Wb       = (const float*)d_in[5];
    const float* Wg       = (const float*)d_in[6];
    const float* conv_q_w = (const float*)d_in[7];
    const float* conv_k_w = (const float*)d_in[8];
    const float* conv_v_w = (const float*)d_in[9];
    const float* A_log    = (const float*)d_in[10];
    const float* dt_bias  = (const float*)d_in[11];
    const float* o_norm_w = (const float*)d_in[12];
    const float* Wo       = (const float*)d_in[13];
    const float* ln1_w    = (const float*)d_in[14];
    const float* ln1_b    = (const float*)d_in[15];
    const float* ln2_w    = (const float*)d_in[16];
    const float* ln2_b    = (const float*)d_in[17];
    const float* ffn_w1   = (const float*)d_in[18];
    const float* ffn_b1   = (const float*)d_in[19];
    const float* ffn_w2   = (const float*)d_in[20];
    const float* ffn_b2   = (const float*)d_in[21];
    float* out = (float*)d_out;

    __half *normh, *xallh, *oh, *hbufh, *ffn1h, *wth;
    float *q, *k, *v, *gg, *bb, *o, *x2;
    cudaGetSymbolAddress((void**)&normh, g_normh);
    cudaGetSymbolAddress((void**)&xallh, g_xallh);
    cudaGetSymbolAddress((void**)&q, g_q);
    cudaGetSymbolAddress((void**)&k, g_k);
    cudaGetSymbolAddress((void**)&v, g_v);
    cudaGetSymbolAddress((void**)&gg, g_gg);
    cudaGetSymbolAddress((void**)&bb, g_bb);
    cudaGetSymbolAddress((void**)&o, g_o);
    cudaGetSymbolAddress((void**)&oh, g_oh);
    cudaGetSymbolAddress((void**)&x2, g_x2);
    cudaGetSymbolAddress((void**)&hbufh, g_hbufh);
    cudaGetSymbolAddress((void**)&ffn1h, g_ffn1h);
    cudaGetSymbolAddress((void**)&wth, g_wth);

    cudaFuncSetAttribute(hgemm<2>, cudaFuncAttributeMaxDynamicSharedMemorySize, SMEM_DYN);
    cudaFuncSetAttribute(hgemm<3>, cudaFuncAttributeMaxDynamicSharedMemorySize, SMEM_DYN);
    cudaFuncSetAttribute(hgemm<4>, cudaFuncAttributeMaxDynamicSharedMemorySize, SMEM_DYN);
    cudaFuncSetAttribute(hgemm<5>, cudaFuncAttributeMaxDynamicSharedMemorySize, SMEM_DYN);

    // 0: all weight transposes
    transpose_all_kernel<<<16384, dim3(32, 8)>>>(Wq, Wk, Wv, Wg, Wo, ffn_w1, ffn_w2, wth);

    // 1: LN1 -> half
    ln_kernel<<<NROWS, 256>>>(x, ln1_w, ln1_b, normh);

    // 2: g/beta (stores exp(g))
    gbeta_kernel<<<NROWS / 8, 256>>>(normh, Wa, Wb, A_log, dt_bias, gg, bb);

    // 3: fused Q|K|V|G projection -> half
    hgemm<5><<<dim3(NQKVG/128, NROWS/128), 256, SMEM_DYN>>>(normh, wth + WT_QKVG, xallh,
                                                            NROWS, NQKVG, Dd, nullptr, nullptr);

    // 4: conv + silu + l2norm for q and k
    conv_l2_kernel<<<NROWS * Hh * 2, 128>>>(xallh, conv_q_w, conv_k_w, q, k);
    // 5: conv + silu for v
    {
        long tv2 = (long)NROWS * (VDIM / 2);
        conv_silu_kernel<<<(unsigned)((tv2 + 255) / 256), 256>>>(xallh, 2048, conv_v_w, v, tv2);
    }

    // 6: scan (unroll-2, exp(g) hoisted)
    scan_kernel<<<Bb * Hh * 8, 256>>>(q, k, v, gg, bb, o);

    // 7: gated RMSNorm -> half
    rmsgate_kernel<<<NROWS * Hh, 256>>>(o, xallh, o_norm_w, oh);

    // 8: x2 = x + oh @ WoT
    hgemm<3><<<dim3(Dd/128, NROWS/128), 256, SMEM_DYN>>>(oh, wth + WT_O, x2,
                                                         NROWS, Dd, VDIM, nullptr, x);

    // 9: LN2 + FFN
    ln_kernel<<<NROWS, 256>>>(x2, ln2_w, ln2_b, hbufh);
    hgemm<2><<<dim3(FFND/128, NROWS/128), 256, SMEM_DYN>>>(hbufh, wth + WT_F1, ffn1h,
                                                           NROWS, FFND, Dd, ffn_b1, nullptr);
    hgemm<4><<<dim3(Dd/128, NROWS/128), 256, SMEM_DYN>>>(ffn1h, wth + WT_F2, out,
                                                         NROWS, Dd, FFND, ffn_b2, x2);
}

// round 16
// speedup vs baseline: 1.1572x; 1.0417x over previous
#include <cuda_runtime.h>
#include <cuda_fp16.h>
#include <math.h>
#include <stdint.h>

#define Bb   4
#define Tt   2048
#define Dd   1024
#define Hh   4
#define DKk  256
#define DVv  512
#define KDIM 1024
#define VDIM 2048
#define FFND 4096
#define NROWS (Bb*Tt)   /* 8192 */
#define NQKVG 6144

// ---------------- scratch ----------------
__device__ __half  g_normh[NROWS*Dd];
__device__ __half  g_xallh[(size_t)NROWS*NQKVG];
__device__ float   g_q[NROWS*KDIM];
__device__ float   g_k[NROWS*KDIM];
__device__ float   g_v[NROWS*VDIM];
__device__ float   g_gg[NROWS*Hh];     /* holds exp(g) */
__device__ float   g_bb[NROWS*Hh];
__device__ float   g_o[NROWS*VDIM];
__device__ __half  g_oh[NROWS*VDIM];
__device__ float   g_x2[NROWS*Dd];
__device__ __half  g_hbufh[NROWS*Dd];
__device__ __half  g_ffn1h[(size_t)NROWS*FFND];
__device__ __half  g_wth[16*1024*1024];
#define WT_QKVG 0
#define WT_O   (6*1024*1024)
#define WT_F1  (8*1024*1024)
#define WT_F2  (12*1024*1024)

// ---------------- helpers ----------------
__device__ __forceinline__ float sigmoidf_(float x) { return 1.0f / (1.0f + expf(-x)); }
__device__ __forceinline__ float siluf_(float x)    { return x * sigmoidf_(x); }
__device__ __forceinline__ float geluf_(float x)    { return 0.5f * x * (1.0f + erff(x * 0.70710678118654752f)); }
__device__ __forceinline__ float softplusf_(float x){ return (x > 20.0f) ? x : log1pf(expf(x)); }
__device__ __forceinline__ uint32_t smem_u32(const void* p) {
    uint32_t a;
    asm("{ .reg .u64 t; cvta.to.shared.u64 t, %1; cvt.u32.u64 %0, t; }" : "=r"(a) : "l"(p));
    return a;
}
__device__ __forceinline__ void cpa16(uint32_t dst, const void* src) {
    asm volatile("cp.async.cg.shared.global [%0], [%1], 16;" :: "r"(dst), "l"(src));
}
__device__ __forceinline__ void cpa4(uint32_t dst, const void* src) {
    asm volatile("cp.async.ca.shared.global [%0], [%1], 4;" :: "r"(dst), "l"(src));
}
__device__ __forceinline__ void ldm4(uint32_t* r, uint32_t addr) {
    asm volatile("ldmatrix.sync.aligned.m8n8.x4.shared.b16 {%0,%1,%2,%3}, [%4];"
        : "=r"(r[0]), "=r"(r[1]), "=r"(r[2]), "=r"(r[3]) : "r"(addr));
}
#define SWZ(o) ((o) ^ (((o) >> 3) & 0x70))

typedef unsigned long long u64t;
#define FMA2(d, a, b, c) asm("fma.rn.f32x2 %0, %1, %2, %3;" : "=l"(d) : "l"(a), "l"(b), "l"(c))
#define MUL2(d, a, b)    asm("mul.rn.f32x2 %0, %1, %2;"     : "=l"(d) : "l"(a), "l"(b))
#define ADD2(d, a, b)    asm("add.rn.f32x2 %0, %1, %2;"     : "=l"(d) : "l"(a), "l"(b))
#define PACK2(d, lo, hi) asm("mov.b64 %0, {%1, %2};" : "=l"(d) : "f"(lo), "f"(hi))
#define UNPK2(lo, hi, s) asm("mov.b64 {%0, %1}, %2;" : "=f"(lo), "=f"(hi) : "l"(s))

// ---------------- ONE fused transpose launch: 7 matrices, src[K,N] -> half dst[N,K] ----------------
__global__ void transpose_all_kernel(const float* __restrict__ Wq, const float* __restrict__ Wk,
                                     const float* __restrict__ Wv, const float* __restrict__ Wg,
                                     const float* __restrict__ Wo, const float* __restrict__ F1,
                                     const float* __restrict__ F2, __half* __restrict__ wth) {
    const int cum[7] = {1024, 2048, 4096, 6144, 8192, 12288, 16384};
    const int Ks[7]  = {1024, 1024, 1024, 1024, 2048, 1024, 4096};
    const int Ns[7]  = {1024, 1024, 2048, 2048, 1024, 4096, 1024};
    const size_t doff[7] = {0, 1024*1024, 2*1024*1024, 4*1024*1024,
                            6*1024*1024, 8*1024*1024, 12*1024*1024};
    int bid = blockIdx.x;
    int m = 0;
    #pragma unroll
    for (int i = 0; i < 7; i++) if (bid >= cum[i]) m = i + 1;
    int lt = bid - (m ? cum[m - 1] : 0);
    const float* srcs[7] = {Wq, Wk, Wv, Wg, Wo, F1, F2};
    const float* src = srcs[m];
    __half* dst = wth + doff[m];
    int K = Ks[m], N = Ns[m];
    int tilesN = N >> 5;
    int nb = (lt % tilesN) * 32, kb = (lt / tilesN) * 32;

    __shared__ float t[32][33];
    int x = threadIdx.x, y = threadIdx.y;
    #pragma unroll
    for (int i = 0; i < 4; i++)
        t[y + 8 * i][x] = src[(size_t)(kb + y + 8 * i) * N + nb + x];
    __syncthreads();
    #pragma unroll
    for (int i = 0; i < 4; i++)
        dst[(size_t)(nb + y + 8 * i) * K + kb + x] = __float2half(t[x][y + 8 * i]);
}

// ---------------- fp16 mma.sync GEMM 128x128, 3-stage cp.async, single barrier/iter ----------------
// EPI: 2 half bias+gelu | 3 float +res | 4 float bias+res | 5 half none
#define STG_BYTES 32768
#define SMEM_DYN (3 * STG_BYTES)

template<int EPI>
__global__ void __launch_bounds__(256)
hgemm(const __half* __restrict__ A, const __half* __restrict__ Bt, void* __restrict__ Cv,
      int M_, int N_, int K_, const float* __restrict__ bias, const float* __restrict__ res) {
    extern __shared__ char sm[];
    uint32_t sbase = smem_u32(sm);
    int tid = threadIdx.x, wid = tid >> 5, lane = tid & 31;
    int g = lane >> 2, tg = lane & 3;
    int bm = blockIdx.y * 128, bn = blockIdx.x * 128;
    int wm = (wid & 1) * 64, wn = (wid >> 1) * 32;

    int lrow = tid >> 1, lc0 = (tid & 1) * 4;
    const __half* gA = A + (size_t)(bm + lrow) * K_ + lc0 * 8;
    const __half* gB = Bt + (size_t)(bn + lrow) * K_ + lc0 * 8;
    uint32_t sAo[4], sBo[4];
    #pragma unroll
    for (int i = 0; i < 4; i++) {
        uint32_t off = lrow * 128 + (lc0 + i) * 16;
        sAo[i] = SWZ(off);
        sBo[i] = 16384 + SWZ(off);
    }
    auto load_stage = [&](int chunk, int stage) {
        uint32_t st = sbase + stage * STG_BYTES;
        const __half* a = gA + chunk * 64;
        const __half* b = gB + chunk * 64;
        #pragma unroll
        for (int i = 0; i < 4; i++) cpa16(st + sAo[i], a + i * 8);
        #pragma unroll
        for (int i = 0; i < 4; i++) cpa16(st + sBo[i], b + i * 8);
        asm volatile("cp.async.commit_group;" ::: "memory");
    };

    int arow = lane & 15;
    int acb  = (lane >> 4) * 16;
    int bsel = lane >> 3;
    int brow = (lane & 7) + ((bsel & 2) ? 8 : 0);
    int bcb  = (bsel & 1) * 16;
    uint32_t aBase[4], bBase[2];
    #pragma unroll
    for (int mt = 0; mt < 4; mt++)
        aBase[mt] = (wm + mt * 16 + arow) * 128 + acb;
    #pragma unroll
    for (int np = 0; np < 2; np++)
        bBase[np] = 16384 + (wn + np * 16 + brow) * 128 + bcb;

    float acc[4][4][4];
    #pragma unroll
    for (int i = 0; i < 4; i++)
        #pragma unroll
        for (int j = 0; j < 4; j++)
            #pragma unroll
            for (int r = 0; r < 4; r++) acc[i][j][r] = 0.f;

    const int NK = K_ >> 6;
    load_stage(0, 0);
    load_stage(1, 1);

    for (int k = 0; k < NK; k++) {
        int sk = k - (k / 3) * 3;
        asm volatile("cp.async.wait_group %0;" :: "n"(1) : "memory");
        __syncthreads();

        if (k + 2 < NK) load_stage(k + 2, (k + 2) - ((k + 2) / 3) * 3);
        else asm volatile("cp.async.commit_group;" ::: "memory");

        uint32_t st = sbase + sk * STG_BYTES;
        #pragma unroll
        for (int kk = 0; kk < 4; kk++) {
            int kbyte = kk * 32;
            uint32_t af[4][4], bf[4][2];
            #pragma unroll
            for (int mt = 0; mt < 4; mt++)
                ldm4(af[mt], st + SWZ(aBase[mt] + kbyte));
            #pragma unroll
            for (int np = 0; np < 2; np++) {
                uint32_t r4[4];
                ldm4(r4, st + SWZ(bBase[np] + kbyte));
                bf[2 * np][0] = r4[0]; bf[2 * np][1] = r4[1];
                bf[2 * np + 1][0] = r4[2]; bf[2 * np + 1][1] = r4[3];
            }
            #pragma unroll
            for (int mt = 0; mt < 4; mt++)
                #pragma unroll
                for (int nt = 0; nt < 4; nt++)
                    asm volatile(
                        "mma.sync.aligned.m16n8k16.row.col.f32.f16.f16.f32 "
                        "{%0,%1,%2,%3}, {%4,%5,%6,%7}, {%8,%9}, {%0,%1,%2,%3};"
                        : "+f"(acc[mt][nt][0]), "+f"(acc[mt][nt][1]),
                          "+f"(acc[mt][nt][2]), "+f"(acc[mt][nt][3])
                        : "r"(af[mt][0]), "r"(af[mt][1]), "r"(af[mt][2]), "r"(af[mt][3]),
                          "r"(bf[nt][0]), "r"(bf[nt][1]));
        }
    }

    float* Cf = (float*)Cv;
    __half* Ch = (__half*)Cv;
    #pragma unroll
    for (int mt = 0; mt < 4; mt++) {
        #pragma unroll
        for (int nt = 0; nt < 4; nt++) {
            int col = bn + wn + nt * 8 + 2 * tg;
            float b0 = 0.f, b1 = 0.f;
            if (EPI == 2 || EPI == 4) { b0 = bias[col]; b1 = bias[col + 1]; }
            #pragma unroll
            for (int h2 = 0; h2 < 2; h2++) {
                int row = bm + wm + mt * 16 + g + h2 * 8;
                float v0 = acc[mt][nt][2 * h2], v1 = acc[mt][nt][2 * h2 + 1];
                if (EPI == 2 || EPI == 4) { v0 += b0; v1 += b1; }
                if (EPI == 2 || EPI == 5) {
                    __half2 hv;
                    hv.x = __float2half(EPI == 2 ? geluf_(v0) : v0);
                    hv.y = __float2half(EPI == 2 ? geluf_(v1) : v1);
                    *(__half2*)(Ch + (size_t)row * N_ + col) = hv;
                } else {
                    if (EPI == 3 || EPI == 4) {
                        float2 rr = *(const float2*)(res + (size_t)row * N_ + col);
                        v0 += rr.x; v1 += rr.y;
                    }
                    float2 o2; o2.x = v0; o2.y = v1;
                    *(float2*)(Cf + (size_t)row * N_ + col) = o2;
                }
            }
        }
    }
}

// ---------------- LayerNorm -> half ----------------
__global__ void ln_kernel(const float* __restrict__ x, const float* __restrict__ w,
                          const float* __restrict__ b, __half* __restrict__ out) {
    int row = blockIdx.x;
    const float* xr = x + (size_t)row * Dd;
    float s1 = 0.f, s2 = 0.f;
    float vals[4];
    #pragma unroll
    for (int i = 0; i < 4; i++) {
        float v = xr[threadIdx.x + i * 256];
        vals[i] = v; s1 += v; s2 += v * v;
    }
    __shared__ float sh[2][8];
    int lane = threadIdx.x & 31, wid = threadIdx.x >> 5;
    #pragma unroll
    for (int off = 16; off > 0; off >>= 1) {
        s1 += __shfl_xor_sync(0xffffffffu, s1, off);
        s2 += __shfl_xor_sync(0xffffffffu, s2, off);
    }
    if (lane == 0) { sh[0][wid] = s1; sh[1][wid] = s2; }
    __syncthreads();
    if (threadIdx.x == 0) {
        float a = 0.f, c = 0.f;
        #pragma unroll
        for (int i = 0; i < 8; i++) { a += sh[0][i]; c += sh[1][i]; }
        sh[0][0] = a; sh[1][0] = c;
    }
    __syncthreads();
    float mean = sh[0][0] * (1.0f / Dd);
    float var  = sh[1][0] * (1.0f / Dd) - mean * mean;
    float inv  = rsqrtf(var + 1e-5f);
    #pragma unroll
    for (int i = 0; i < 4; i++) {
        int c = threadIdx.x + i * 256;
        out[(size_t)row * Dd + c] = __float2half((vals[i] - mean) * inv * w[c] + b[c]);
    }
}

// ---------------- g / beta : stores exp(g) directly ----------------
__global__ void gbeta_kernel(const __half* __restrict__ normed, const float* __restrict__ Wa,
                             const float* __restrict__ Wb, const float* __restrict__ A_log,
                             const float* __restrict__ dt_bias, float* __restrict__ eg,
                             float* __restrict__ beta) {
    int row = blockIdx.x * 8 + (threadIdx.x >> 5);
    int lane = threadIdx.x & 31;
    const __half* xr = normed + (size_t)row * Dd;
    float acc[8];
    #pragma unroll
    for (int j = 0; j < 8; j++) acc[j] = 0.f;
    for (int k = lane; k < Dd; k += 32) {
        float xv = __half2float(xr[k]);
        const float* wa = Wa + k * 4;
        const float* wb = Wb + k * 4;
        #pragma unroll
        for (int j = 0; j < 4; j++) { acc[j] += xv * wa[j]; acc[4 + j] += xv * wb[j]; }
    }
    #pragma unroll
    for (int off = 16; off > 0; off >>= 1)
        #pragma unroll
        for (int j = 0; j < 8; j++) acc[j] += __shfl_xor_sync(0xffffffffu, acc[j], off);
    if (lane < 4) {
        float xa = acc[lane] + dt_bias[lane];
        float gval = -expf(A_log[lane]) * softplusf_(xa);
        eg[row * 4 + lane] = expf(gval);
        beta[row * 4 + lane] = sigmoidf_(acc[4 + lane]);
    }
}

// ---------------- fused conv+SiLU+l2norm for q AND k (half2 vectorized) ----------------
__global__ void conv_l2_kernel(const __half* __restrict__ xall,
                               const float* __restrict__ wq, const float* __restrict__ wk,
                               float* __restrict__ qout, float* __restrict__ kout) {
    int bid = blockIdx.x;
    bool isq = bid < NROWS * Hh;
    int rowh = isq ? bid : bid - NROWS * Hh;
    long row = rowh >> 2;
    int h = rowh & 3;
    int t = (int)(row & (Tt - 1));
    long bbase = row - t;
    int c = h * DKk + threadIdx.x * 2;
    int coff = isq ? 0 : 1024;
    const float* w = isq ? wq : wk;
    float wA[2][4] = {{w[c*4+0], w[c*4+1], w[c*4+2], w[c*4+3]},
                      {w[c*4+4], w[c*4+5], w[c*4+6], w[c*4+7]}};
    float a0 = 0.f, a1 = 0.f;
    #pragma unroll
    for (int i = 0; i < 4; i++) {
        int tt = t - 3 + i;
        if (tt >= 0) {
            __half2 hv = *(const __half2*)(xall + (bbase + tt) * (long)NQKVG + coff + c);
            float2 fv = __half22float2(hv);
            a0 += fv.x * wA[0][i];
            a1 += fv.y * wA[1][i];
        }
    }
    float v0 = siluf_(a0), v1 = siluf_(a1);
    float ss = v0 * v0 + v1 * v1;
    __shared__ float sh[4];
    int lane = threadIdx.x & 31, wid = threadIdx.x >> 5;
    #pragma unroll
    for (int off = 16; off > 0; off >>= 1) ss += __shfl_xor_sync(0xffffffffu, ss, off);
    if (lane == 0) sh[wid] = ss;
    __syncthreads();
    if (threadIdx.x == 0) sh[0] = sh[0] + sh[1] + sh[2] + sh[3];
    __syncthreads();
    float sc = (isq ? 0.0625f : 1.0f) * rsqrtf(sh[0] + 1e-6f);
    float* outp = isq ? qout : kout;
    float2 o2; o2.x = v0 * sc; o2.y = v1 * sc;
    *(float2*)(outp + row * KDIM + c) = o2;
}

// ---------------- conv + SiLU for V (half2 vectorized) ----------------
__global__ void conv_silu_kernel(const __half* __restrict__ x, int coff,
                                 const float* __restrict__ w,
                                 float* __restrict__ y, long total2) {
    long idx = (long)blockIdx.x * blockDim.x + threadIdx.x;
    if (idx >= total2) return;
    int c = (int)(idx % (VDIM / 2)) * 2;
    long bt = idx / (VDIM / 2);
    int t = (int)(bt % Tt);
    long bbase = (bt / Tt) * Tt;
    const float* w4 = w + c * 4;
    float a0 = 0.f, a1 = 0.f;
    #pragma unroll
    for (int i = 0; i < 4; i++) {
        int tt = t - 3 + i;
        if (tt >= 0) {
            __half2 hv = *(const __half2*)(x + (bbase + tt) * (long)NQKVG + coff + c);
            float2 fv = __half22float2(hv);
            a0 += fv.x * w4[i];
            a1 += fv.y * w4[4 + i];
        }
    }
    float2 o2; o2.x = siluf_(a0); o2.y = siluf_(a1);
    *(float2*)(y + bt * VDIM + c) = o2;
}

// ---------------- gated delta rule scan: ring depth 16, UNROLL-4 (one barrier per 4 steps) ----------------
#define KSTR 68
#define RD 16
__global__ void __launch_bounds__(256)
scan_kernel(const float* __restrict__ q, const float* __restrict__ k, const float* __restrict__ v,
            const float* __restrict__ egp_, const float* __restrict__ beta, float* __restrict__ o) {
    int b  = blockIdx.x >> 5;
    int h  = (blockIdx.x >> 3) & 3;
    int sl = blockIdx.x & 7;
    int v0 = sl * 64;
    int tid = threadIdx.x;
    int kb = tid & 3, vi = tid >> 2;
    int kb68 = kb * KSTR;

    __shared__ float qs[RD][4 * KSTR], ks[RD][4 * KSTR], vs[RD][64], sgb[RD][2];

    const float* qp = q + (size_t)b * Tt * KDIM + h * DKk + tid;
    const float* kp = k + (size_t)b * Tt * KDIM + h * DKk + tid;
    const float* vp = v + (size_t)b * Tt * VDIM + h * DVv + v0 + tid;
    const float* gp = egp_ + (size_t)b * Tt * Hh + h;
    const float* bp = beta + (size_t)b * Tt * Hh + h;

    uint32_t qdst0 = smem_u32(&qs[0][kb * KSTR + vi]);
    uint32_t kdst0 = smem_u32(&ks[0][kb * KSTR + vi]);
    uint32_t vdst0 = smem_u32(&vs[0][tid & 63]);
    uint32_t gdst0 = smem_u32(&sgb[0][0]);
    const uint32_t QKROW = 4 * KSTR * 4;

    auto prefetch = [&](int t) {
        int st = t & (RD - 1);
        cpa4(qdst0 + st * QKROW, qp + (size_t)t * KDIM);
        cpa4(kdst0 + st * QKROW, kp + (size_t)t * KDIM);
        if (tid < 64)       cpa4(vdst0 + st * 256, vp + (size_t)t * VDIM);
        else if (tid == 64) cpa4(gdst0 + st * 8,     gp + (size_t)t * Hh);
        else if (tid == 65) cpa4(gdst0 + st * 8 + 4, bp + (size_t)t * Hh);
    };

    // prologue: steps 0..11 in 3 groups of 4
    #pragma unroll
    for (int i = 0; i < 3; i++) {
        #pragma unroll
        for (int j = 0; j < 4; j++) prefetch(4 * i + j);
        asm volatile("cp.async.commit_group;" ::: "memory");
    }

    u64t S2[32];
    #pragma unroll
    for (int j = 0; j < 32; j++) S2[j] = 0ull;
    u64t kreg2[32];

    float* obase = o + (size_t)b * Tt * VDIM + h * DVv + v0 + vi;

    for (int t = 0; t < Tt; t += 4) {
        // groups complete through step t+3; slots t+4..t+11 in flight
        asm volatile("cp.async.wait_group %0;" :: "n"(2) : "memory");
        __syncthreads();

        // refill slots (t+12..t+15)&15 == (t-4..t-1)&15, read in the previous iteration
        if (t + 12 < Tt) {
            prefetch(t + 12);
            if (t + 13 < Tt) prefetch(t + 13);
            if (t + 14 < Tt) prefetch(t + 14);
            if (t + 15 < Tt) prefetch(t + 15);
        }
        asm volatile("cp.async.commit_group;" ::: "memory");

        #pragma unroll
        for (int u = 0; u < 4; u++) {
            int tc = t + u;
            int st = tc & (RD - 1);

            float eg = sgb[st][0];
            float bt = sgb[st][1];
            u64t eg2; PACK2(eg2, eg, eg);

            u64t p2a = 0ull, p2b = 0ull;
            #pragma unroll
            for (int jj = 0; jj < 16; jj++) {
                ulonglong2 kv = *(const ulonglong2*)&ks[st][kb68 + 4 * jj];
                kreg2[2 * jj]     = kv.x;
                kreg2[2 * jj + 1] = kv.y;
                FMA2(p2a, kv.x, S2[2 * jj],     p2a);
                FMA2(p2b, kv.y, S2[2 * jj + 1], p2b);
            }
            ADD2(p2a, p2a, p2b);
            float plo, phi;
            UNPK2(plo, phi, p2a);
            float partial = plo + phi;
            partial += __shfl_xor_sync(0xffffffffu, partial, 1);
            partial += __shfl_xor_sync(0xffffffffu, partial, 2);
            float delta = (vs[st][vi] - eg * partial) * bt;
            u64t d2; PACK2(d2, delta, delta);

            u64t o2a = 0ull, o2b = 0ull;
            #pragma unroll
            for (int jj = 0; jj < 16; jj++) {
                ulonglong2 qv = *(const ulonglong2*)&qs[st][kb68 + 4 * jj];
                u64t t0, t1;
                MUL2(t0, kreg2[2 * jj],     d2);
                MUL2(t1, kreg2[2 * jj + 1], d2);
                FMA2(S2[2 * jj],     eg2, S2[2 * jj],     t0);
                FMA2(S2[2 * jj + 1], eg2, S2[2 * jj + 1], t1);
                FMA2(o2a, qv.x, S2[2 * jj],     o2a);
                FMA2(o2b, qv.y, S2[2 * jj + 1], o2b);
            }
            ADD2(o2a, o2a, o2b);
            float olo, ohi;
            UNPK2(olo, ohi, o2a);
            float opart = olo + ohi;
            opart += __shfl_xor_sync(0xffffffffu, opart, 1);
            opart += __shfl_xor_sync(0xffffffffu, opart, 2);
            if (kb == 0) obase[(size_t)tc * VDIM] = opart;
        }
    }
}

// ---------------- gated RMSNorm + silu(gate) -> half ----------------
__global__ void rmsgate_kernel(const float* __restrict__ o, const __half* __restrict__ xall,
                               const float* __restrict__ onw, __half* __restrict__ oh) {
    int rowh = blockIdx.x;
    long row = rowh >> 2;
    int h = rowh & 3;
    const float* op = o + row * VDIM + h * DVv;
    const __half* gp = xall + row * (long)NQKVG + 4096 + h * DVv;
    __half* ohp = oh + row * VDIM + h * DVv;
    float v1 = op[threadIdx.x], v2 = op[threadIdx.x + 256];
    float ss = v1 * v1 + v2 * v2;
    __shared__ float sh[8];
    int lane = threadIdx.x & 31, wid = threadIdx.x >> 5;
    #pragma unroll
    for (int off = 16; off > 0; off >>= 1) ss += __shfl_xor_sync(0xffffffffu, ss, off);
    if (lane == 0) sh[wid] = ss;
    __syncthreads();
    if (threadIdx.x == 0) {
        float a = 0.f;
        #pragma unroll
        for (int i = 0; i < 8; i++) a += sh[i];
        sh[0] = a;
    }
    __syncthreads();
    float scale = rsqrtf(sh[0] * (1.0f / DVv) + 1e-5f);
    int c1 = threadIdx.x, c2 = threadIdx.x + 256;
    ohp[c1] = __float2half(v1 * scale * onw[c1] * siluf_(__half2float(gp[c1])));
    ohp[c2] = __float2half(v2 * scale * onw[c2] * siluf_(__half2float(gp[c2])));
}

// ---------------- launcher ----------------
extern "C" void kernel_launch(void* const* d_in, const int* in_sizes, int n_in,
                              void* d_out, int out_size) {
    const float* x        = (const float*)d_in[0];
    const float* Wq       = (const float*)d_in[1];
    const float* Wk       = (const float*)d_in[2];
    const float* Wv       = (const float*)d_in[3];
    const float* Wa       = (const float*)d_in[4];
    const float* Wb       = (const float*)d_in[5];
    const float* Wg       = (const float*)d_in[6];
    const float* conv_q_w = (const float*)d_in[7];
    const float* conv_k_w = (const float*)d_in[8];
    const float* conv_v_w = (const float*)d_in[9];
    const float* A_log    = (const float*)d_in[10];
    const float* dt_bias  = (const float*)d_in[11];
    const float* o_norm_w = (const float*)d_in[12];
    const float* Wo       = (const float*)d_in[13];
    const float* ln1_w    = (const float*)d_in[14];
    const float* ln1_b    = (const float*)d_in[15];
    const float* ln2_w    = (const float*)d_in[16];
    const float* ln2_b    = (const float*)d_in[17];
    const float* ffn_w1   = (const float*)d_in[18];
    const float* ffn_b1   = (const float*)d_in[19];
    const float* ffn_w2   = (const float*)d_in[20];
    const float* ffn_b2   = (const float*)d_in[21];
    float* out = (float*)d_out;

    __half *normh, *xallh, *oh, *hbufh, *ffn1h, *wth;
    float *q, *k, *v, *gg, *bb, *o, *x2;
    cudaGetSymbolAddress((void**)&normh, g_normh);
    cudaGetSymbolAddress((void**)&xallh, g_xallh);
    cudaGetSymbolAddress((void**)&q, g_q);
    cudaGetSymbolAddress((void**)&k, g_k);
    cudaGetSymbolAddress((void**)&v, g_v);
    cudaGetSymbolAddress((void**)&gg, g_gg);
    cudaGetSymbolAddress((void**)&bb, g_bb);
    cudaGetSymbolAddress((void**)&o, g_o);
    cudaGetSymbolAddress((void**)&oh, g_oh);
    cudaGetSymbolAddress((void**)&x2, g_x2);
    cudaGetSymbolAddress((void**)&hbufh, g_hbufh);
    cudaGetSymbolAddress((void**)&ffn1h, g_ffn1h);
    cudaGetSymbolAddress((void**)&wth, g_wth);

    cudaFuncSetAttribute(hgemm<2>, cudaFuncAttributeMaxDynamicSharedMemorySize, SMEM_DYN);
    cudaFuncSetAttribute(hgemm<3>, cudaFuncAttributeMaxDynamicSharedMemorySize, SMEM_DYN);
    cudaFuncSetAttribute(hgemm<4>, cudaFuncAttributeMaxDynamicSharedMemorySize, SMEM_DYN);
    cudaFuncSetAttribute(hgemm<5>, cudaFuncAttributeMaxDynamicSharedMemorySize, SMEM_DYN);

    // 0: all weight transposes
    transpose_all_kernel<<<16384, dim3(32, 8)>>>(Wq, Wk, Wv, Wg, Wo, ffn_w1, ffn_w2, wth);

    // 1: LN1 -> half
    ln_kernel<<<NROWS, 256>>>(x, ln1_w, ln1_b, normh);

    // 2: g/beta (stores exp(g))
    gbeta_kernel<<<NROWS / 8, 256>>>(normh, Wa, Wb, A_log, dt_bias, gg, bb);

    // 3: fused Q|K|V|G projection -> half
    hgemm<5><<<dim3(NQKVG/128, NROWS/128), 256, SMEM_DYN>>>(normh, wth + WT_QKVG, xallh,
                                                            NROWS, NQKVG, Dd, nullptr, nullptr);

    // 4: conv + silu + l2norm for q and k
    conv_l2_kernel<<<NROWS * Hh * 2, 128>>>(xallh, conv_q_w, conv_k_w, q, k);
    // 5: conv + silu for v
    {
        long tv2 = (long)NROWS * (VDIM / 2);
        conv_silu_kernel<<<(unsigned)((tv2 + 255) / 256), 256>>>(xallh, 2048, conv_v_w, v, tv2);
    }

    // 6: scan (unroll-4, ring 16)
    scan_kernel<<<Bb * Hh * 8, 256>>>(q, k, v, gg, bb, o);

    // 7: gated RMSNorm -> half
    rmsgate_kernel<<<NROWS * Hh, 256>>>(o, xallh, o_norm_w, oh);

    // 8: x2 = x + oh @ WoT
    hgemm<3><<<dim3(Dd/128, NROWS/128), 256, SMEM_DYN>>>(oh, wth + WT_O, x2,
                                                         NROWS, Dd, VDIM, nullptr, x);

    // 9: LN2 + FFN
    ln_kernel<<<NROWS, 256>>>(x2, ln2_w, ln2_b, hbufh);
    hgemm<2><<<dim3(FFND/128, NROWS/128), 256, SMEM_DYN>>>(hbufh, wth + WT_F1, ffn1h,
                                                           NROWS, FFND, Dd, ffn_b1, nullptr);
    hgemm<4><<<dim3(Dd/128, NROWS/128), 256, SMEM_DYN>>>(ffn1h, wth + WT_F2, out,
                                                         NROWS, Dd, FFND, ffn_b2, x2);
}

// round 17
// speedup vs baseline: 1.1717x; 1.0125x over previous
#include <cuda_runtime.h>
#include <cuda_fp16.h>
#include <math.h>
#include <stdint.h>

#define Bb   4
#define Tt   2048
#define Dd   1024
#define Hh   4
#define DKk  256
#define DVv  512
#define KDIM 1024
#define VDIM 2048
#define FFND 4096
#define NROWS (Bb*Tt)   /* 8192 */
#define NQKVG 6144

// ---------------- scratch ----------------
__device__ __half  g_normh[NROWS*Dd];
__device__ __half  g_xallh[(size_t)NROWS*NQKVG];
__device__ float   g_q[NROWS*KDIM];
__device__ float   g_k[NROWS*KDIM];
__device__ float   g_v[NROWS*VDIM];
__device__ float   g_gg[NROWS*Hh];     /* holds exp(g) */
__device__ float   g_bb[NROWS*Hh];
__device__ float   g_o[NROWS*VDIM];
__device__ __half  g_oh[NROWS*VDIM];
__device__ float   g_x2[NROWS*Dd];
__device__ __half  g_hbufh[NROWS*Dd];
__device__ __half  g_ffn1h[(size_t)NROWS*FFND];
__device__ __half  g_wth[16*1024*1024];
#define WT_QKVG 0
#define WT_O   (6*1024*1024)
#define WT_F1  (8*1024*1024)
#define WT_F2  (12*1024*1024)

// ---------------- helpers ----------------
__device__ __forceinline__ float sigmoidf_(float x) { return 1.0f / (1.0f + expf(-x)); }
__device__ __forceinline__ float siluf_(float x)    { return x * sigmoidf_(x); }
__device__ __forceinline__ float geluf_(float x)    { return 0.5f * x * (1.0f + erff(x * 0.70710678118654752f)); }
__device__ __forceinline__ float softplusf_(float x){ return (x > 20.0f) ? x : log1pf(expf(x)); }
__device__ __forceinline__ uint32_t smem_u32(const void* p) {
    uint32_t a;
    asm("{ .reg .u64 t; cvta.to.shared.u64 t, %1; cvt.u32.u64 %0, t; }" : "=r"(a) : "l"(p));
    return a;
}
__device__ __forceinline__ void cpa16(uint32_t dst, const void* src) {
    asm volatile("cp.async.cg.shared.global [%0], [%1], 16;" :: "r"(dst), "l"(src));
}
__device__ __forceinline__ void cpa4(uint32_t dst, const void* src) {
    asm volatile("cp.async.ca.shared.global [%0], [%1], 4;" :: "r"(dst), "l"(src));
}
__device__ __forceinline__ void ldm4(uint32_t* r, uint32_t addr) {
    asm volatile("ldmatrix.sync.aligned.m8n8.x4.shared.b16 {%0,%1,%2,%3}, [%4];"
        : "=r"(r[0]), "=r"(r[1]), "=r"(r[2]), "=r"(r[3]) : "r"(addr));
}
#define SWZ(o) ((o) ^ (((o) >> 3) & 0x70))

typedef unsigned long long u64t;
#define FMA2(d, a, b, c) asm("fma.rn.f32x2 %0, %1, %2, %3;" : "=l"(d) : "l"(a), "l"(b), "l"(c))
#define MUL2(d, a, b)    asm("mul.rn.f32x2 %0, %1, %2;"     : "=l"(d) : "l"(a), "l"(b))
#define ADD2(d, a, b)    asm("add.rn.f32x2 %0, %1, %2;"     : "=l"(d) : "l"(a), "l"(b))
#define PACK2(d, lo, hi) asm("mov.b64 %0, {%1, %2};" : "=l"(d) : "f"(lo), "f"(hi))
#define UNPK2(lo, hi, s) asm("mov.b64 {%0, %1}, %2;" : "=f"(lo), "=f"(hi) : "l"(s))

// ---------------- ONE fused transpose launch: 7 matrices, src[K,N] -> half dst[N,K] ----------------
__global__ void transpose_all_kernel(const float* __restrict__ Wq, const float* __restrict__ Wk,
                                     const float* __restrict__ Wv, const float* __restrict__ Wg,
                                     const float* __restrict__ Wo, const float* __restrict__ F1,
                                     const float* __restrict__ F2, __half* __restrict__ wth) {
    const int cum[7] = {1024, 2048, 4096, 6144, 8192, 12288, 16384};
    const int Ks[7]  = {1024, 1024, 1024, 1024, 2048, 1024, 4096};
    const int Ns[7]  = {1024, 1024, 2048, 2048, 1024, 4096, 1024};
    const size_t doff[7] = {0, 1024*1024, 2*1024*1024, 4*1024*1024,
                            6*1024*1024, 8*1024*1024, 12*1024*1024};
    int bid = blockIdx.x;
    int m = 0;
    #pragma unroll
    for (int i = 0; i < 7; i++) if (bid >= cum[i]) m = i + 1;
    int lt = bid - (m ? cum[m - 1] : 0);
    const float* srcs[7] = {Wq, Wk, Wv, Wg, Wo, F1, F2};
    const float* src = srcs[m];
    __half* dst = wth + doff[m];
    int K = Ks[m], N = Ns[m];
    int tilesN = N >> 5;
    int nb = (lt % tilesN) * 32, kb = (lt / tilesN) * 32;

    __shared__ float t[32][33];
    int x = threadIdx.x, y = threadIdx.y;
    #pragma unroll
    for (int i = 0; i < 4; i++)
        t[y + 8 * i][x] = src[(size_t)(kb + y + 8 * i) * N + nb + x];
    __syncthreads();
    #pragma unroll
    for (int i = 0; i < 4; i++)
        dst[(size_t)(nb + y + 8 * i) * K + kb + x] = __float2half(t[x][y + 8 * i]);
}

// ---------------- fp16 mma.sync GEMM 128x128, 3-stage cp.async, single barrier/iter ----------------
// EPI: 2 half bias+gelu | 3 float +res | 4 float bias+res | 5 half none
#define STG_BYTES 32768
#define SMEM_DYN (3 * STG_BYTES)

template<int EPI>
__global__ void __launch_bounds__(256)
hgemm(const __half* __restrict__ A, const __half* __restrict__ Bt, void* __restrict__ Cv,
      int M_, int N_, int K_, const float* __restrict__ bias, const float* __restrict__ res) {
    extern __shared__ char sm[];
    uint32_t sbase = smem_u32(sm);
    int tid = threadIdx.x, wid = tid >> 5, lane = tid & 31;
    int g = lane >> 2, tg = lane & 3;
    int bm = blockIdx.y * 128, bn = blockIdx.x * 128;
    int wm = (wid & 1) * 64, wn = (wid >> 1) * 32;

    int lrow = tid >> 1, lc0 = (tid & 1) * 4;
    const __half* gA = A + (size_t)(bm + lrow) * K_ + lc0 * 8;
    const __half* gB = Bt + (size_t)(bn + lrow) * K_ + lc0 * 8;
    uint32_t sAo[4], sBo[4];
    #pragma unroll
    for (int i = 0; i < 4; i++) {
        uint32_t off = lrow * 128 + (lc0 + i) * 16;
        sAo[i] = SWZ(off);
        sBo[i] = 16384 + SWZ(off);
    }
    auto load_stage = [&](int chunk, int stage) {
        uint32_t st = sbase + stage * STG_BYTES;
        const __half* a = gA + chunk * 64;
        const __half* b = gB + chunk * 64;
        #pragma unroll
        for (int i = 0; i < 4; i++) cpa16(st + sAo[i], a + i * 8);
        #pragma unroll
        for (int i = 0; i < 4; i++) cpa16(st + sBo[i], b + i * 8);
        asm volatile("cp.async.commit_group;" ::: "memory");
    };

    int arow = lane & 15;
    int acb  = (lane >> 4) * 16;
    int bsel = lane >> 3;
    int brow = (lane & 7) + ((bsel & 2) ? 8 : 0);
    int bcb  = (bsel & 1) * 16;
    uint32_t aBase[4], bBase[2];
    #pragma unroll
    for (int mt = 0; mt < 4; mt++)
        aBase[mt] = (wm + mt * 16 + arow) * 128 + acb;
    #pragma unroll
    for (int np = 0; np < 2; np++)
        bBase[np] = 16384 + (wn + np * 16 + brow) * 128 + bcb;

    float acc[4][4][4];
    #pragma unroll
    for (int i = 0; i < 4; i++)
        #pragma unroll
        for (int j = 0; j < 4; j++)
            #pragma unroll
            for (int r = 0; r < 4; r++) acc[i][j][r] = 0.f;

    const int NK = K_ >> 6;
    load_stage(0, 0);
    load_stage(1, 1);

    for (int k = 0; k < NK; k++) {
        int sk = k - (k / 3) * 3;
        asm volatile("cp.async.wait_group %0;" :: "n"(1) : "memory");
        __syncthreads();

        if (k + 2 < NK) load_stage(k + 2, (k + 2) - ((k + 2) / 3) * 3);
        else asm volatile("cp.async.commit_group;" ::: "memory");

        uint32_t st = sbase + sk * STG_BYTES;
        #pragma unroll
        for (int kk = 0; kk < 4; kk++) {
            int kbyte = kk * 32;
            uint32_t af[4][4], bf[4][2];
            #pragma unroll
            for (int mt = 0; mt < 4; mt++)
                ldm4(af[mt], st + SWZ(aBase[mt] + kbyte));
            #pragma unroll
            for (int np = 0; np < 2; np++) {
                uint32_t r4[4];
                ldm4(r4, st + SWZ(bBase[np] + kbyte));
                bf[2 * np][0] = r4[0]; bf[2 * np][1] = r4[1];
                bf[2 * np + 1][0] = r4[2]; bf[2 * np + 1][1] = r4[3];
            }
            #pragma unroll
            for (int mt = 0; mt < 4; mt++)
                #pragma unroll
                for (int nt = 0; nt < 4; nt++)
                    asm volatile(
                        "mma.sync.aligned.m16n8k16.row.col.f32.f16.f16.f32 "
                        "{%0,%1,%2,%3}, {%4,%5,%6,%7}, {%8,%9}, {%0,%1,%2,%3};"
                        : "+f"(acc[mt][nt][0]), "+f"(acc[mt][nt][1]),
                          "+f"(acc[mt][nt][2]), "+f"(acc[mt][nt][3])
                        : "r"(af[mt][0]), "r"(af[mt][1]), "r"(af[mt][2]), "r"(af[mt][3]),
                          "r"(bf[nt][0]), "r"(bf[nt][1]));
        }
    }

    float* Cf = (float*)Cv;
    __half* Ch = (__half*)Cv;
    #pragma unroll
    for (int mt = 0; mt < 4; mt++) {
        #pragma unroll
        for (int nt = 0; nt < 4; nt++) {
            int col = bn + wn + nt * 8 + 2 * tg;
            float b0 = 0.f, b1 = 0.f;
            if (EPI == 2 || EPI == 4) { b0 = bias[col]; b1 = bias[col + 1]; }
            #pragma unroll
            for (int h2 = 0; h2 < 2; h2++) {
                int row = bm + wm + mt * 16 + g + h2 * 8;
                float v0 = acc[mt][nt][2 * h2], v1 = acc[mt][nt][2 * h2 + 1];
                if (EPI == 2 || EPI == 4) { v0 += b0; v1 += b1; }
                if (EPI == 2 || EPI == 5) {
                    __half2 hv;
                    hv.x = __float2half(EPI == 2 ? geluf_(v0) : v0);
                    hv.y = __float2half(EPI == 2 ? geluf_(v1) : v1);
                    *(__half2*)(Ch + (size_t)row * N_ + col) = hv;
                } else {
                    if (EPI == 3 || EPI == 4) {
                        float2 rr = *(const float2*)(res + (size_t)row * N_ + col);
                        v0 += rr.x; v1 += rr.y;
                    }
                    float2 o2; o2.x = v0; o2.y = v1;
                    *(float2*)(Cf + (size_t)row * N_ + col) = o2;
                }
            }
        }
    }
}

// ---------------- LayerNorm -> half ----------------
__global__ void ln_kernel(const float* __restrict__ x, const float* __restrict__ w,
                          const float* __restrict__ b, __half* __restrict__ out) {
    int row = blockIdx.x;
    const float* xr = x + (size_t)row * Dd;
    float s1 = 0.f, s2 = 0.f;
    float vals[4];
    #pragma unroll
    for (int i = 0; i < 4; i++) {
        float v = xr[threadIdx.x + i * 256];
        vals[i] = v; s1 += v; s2 += v * v;
    }
    __shared__ float sh[2][8];
    int lane = threadIdx.x & 31, wid = threadIdx.x >> 5;
    #pragma unroll
    for (int off = 16; off > 0; off >>= 1) {
        s1 += __shfl_xor_sync(0xffffffffu, s1, off);
        s2 += __shfl_xor_sync(0xffffffffu, s2, off);
    }
    if (lane == 0) { sh[0][wid] = s1; sh[1][wid] = s2; }
    __syncthreads();
    if (threadIdx.x == 0) {
        float a = 0.f, c = 0.f;
        #pragma unroll
        for (int i = 0; i < 8; i++) { a += sh[0][i]; c += sh[1][i]; }
        sh[0][0] = a; sh[1][0] = c;
    }
    __syncthreads();
    float mean = sh[0][0] * (1.0f / Dd);
    float var  = sh[1][0] * (1.0f / Dd) - mean * mean;
    float inv  = rsqrtf(var + 1e-5f);
    #pragma unroll
    for (int i = 0; i < 4; i++) {
        int c = threadIdx.x + i * 256;
        out[(size_t)row * Dd + c] = __float2half((vals[i] - mean) * inv * w[c] + b[c]);
    }
}

// ---------------- g / beta : stores exp(g) directly ----------------
__global__ void gbeta_kernel(const __half* __restrict__ normed, const float* __restrict__ Wa,
                             const float* __restrict__ Wb, const float* __restrict__ A_log,
                             const float* __restrict__ dt_bias, float* __restrict__ eg,
                             float* __restrict__ beta) {
    int row = blockIdx.x * 8 + (threadIdx.x >> 5);
    int lane = threadIdx.x & 31;
    const __half* xr = normed + (size_t)row * Dd;
    float acc[8];
    #pragma unroll
    for (int j = 0; j < 8; j++) acc[j] = 0.f;
    for (int k = lane; k < Dd; k += 32) {
        float xv = __half2float(xr[k]);
        const float* wa = Wa + k * 4;
        const float* wb = Wb + k * 4;
        #pragma unroll
        for (int j = 0; j < 4; j++) { acc[j] += xv * wa[j]; acc[4 + j] += xv * wb[j]; }
    }
    #pragma unroll
    for (int off = 16; off > 0; off >>= 1)
        #pragma unroll
        for (int j = 0; j < 8; j++) acc[j] += __shfl_xor_sync(0xffffffffu, acc[j], off);
    if (lane < 4) {
        float xa = acc[lane] + dt_bias[lane];
        float gval = -expf(A_log[lane]) * softplusf_(xa);
        eg[row * 4 + lane] = expf(gval);
        beta[row * 4 + lane] = sigmoidf_(acc[4 + lane]);
    }
}

// ---------------- fused conv+SiLU+l2norm for q AND k (half2 vectorized) ----------------
__global__ void conv_l2_kernel(const __half* __restrict__ xall,
                               const float* __restrict__ wq, const float* __restrict__ wk,
                               float* __restrict__ qout, float* __restrict__ kout) {
    int bid = blockIdx.x;
    bool isq = bid < NROWS * Hh;
    int rowh = isq ? bid : bid - NROWS * Hh;
    long row = rowh >> 2;
    int h = rowh & 3;
    int t = (int)(row & (Tt - 1));
    long bbase = row - t;
    int c = h * DKk + threadIdx.x * 2;
    int coff = isq ? 0 : 1024;
    const float* w = isq ? wq : wk;
    float wA[2][4] = {{w[c*4+0], w[c*4+1], w[c*4+2], w[c*4+3]},
                      {w[c*4+4], w[c*4+5], w[c*4+6], w[c*4+7]}};
    float a0 = 0.f, a1 = 0.f;
    #pragma unroll
    for (int i = 0; i < 4; i++) {
        int tt = t - 3 + i;
        if (tt >= 0) {
            __half2 hv = *(const __half2*)(xall + (bbase + tt) * (long)NQKVG + coff + c);
            float2 fv = __half22float2(hv);
            a0 += fv.x * wA[0][i];
            a1 += fv.y * wA[1][i];
        }
    }
    float v0 = siluf_(a0), v1 = siluf_(a1);
    float ss = v0 * v0 + v1 * v1;
    __shared__ float sh[4];
    int lane = threadIdx.x & 31, wid = threadIdx.x >> 5;
    #pragma unroll
    for (int off = 16; off > 0; off >>= 1) ss += __shfl_xor_sync(0xffffffffu, ss, off);
    if (lane == 0) sh[wid] = ss;
    __syncthreads();
    if (threadIdx.x == 0) sh[0] = sh[0] + sh[1] + sh[2] + sh[3];
    __syncthreads();
    float sc = (isq ? 0.0625f : 1.0f) * rsqrtf(sh[0] + 1e-6f);
    float* outp = isq ? qout : kout;
    float2 o2; o2.x = v0 * sc; o2.y = v1 * sc;
    *(float2*)(outp + row * KDIM + c) = o2;
}

// ---------------- conv + SiLU for V (half2 vectorized) ----------------
__global__ void conv_silu_kernel(const __half* __restrict__ x, int coff,
                                 const float* __restrict__ w,
                                 float* __restrict__ y, long total2) {
    long idx = (long)blockIdx.x * blockDim.x + threadIdx.x;
    if (idx >= total2) return;
    int c = (int)(idx % (VDIM / 2)) * 2;
    long bt = idx / (VDIM / 2);
    int t = (int)(bt % Tt);
    long bbase = (bt / Tt) * Tt;
    const float* w4 = w + c * 4;
    float a0 = 0.f, a1 = 0.f;
    #pragma unroll
    for (int i = 0; i < 4; i++) {
        int tt = t - 3 + i;
        if (tt >= 0) {
            __half2 hv = *(const __half2*)(x + (bbase + tt) * (long)NQKVG + coff + c);
            float2 fv = __half22float2(hv);
            a0 += fv.x * w4[i];
            a1 += fv.y * w4[4 + i];
        }
    }
    float2 o2; o2.x = siluf_(a0); o2.y = siluf_(a1);
    *(float2*)(y + bt * VDIM + c) = o2;
}

// ---------------- gated delta rule scan: ring depth 32 (dynamic smem), UNROLL-8 ----------------
#define KSTR 68
#define RD 32
#define QS_OFF 0
#define KS_OFF (RD * 4 * KSTR)              /* 8704 floats */
#define VS_OFF (2 * RD * 4 * KSTR)          /* 17408 */
#define SG_OFF (2 * RD * 4 * KSTR + RD*64)  /* 19456 */
#define SCAN_SMEM ((2 * RD * 4 * KSTR + RD * 64 + RD * 2) * 4)  /* 78080 B */

__global__ void __launch_bounds__(256)
scan_kernel(const float* __restrict__ q, const float* __restrict__ k, const float* __restrict__ v,
            const float* __restrict__ egp_, const float* __restrict__ beta, float* __restrict__ o) {
    extern __shared__ float dynsm[];
    int b  = blockIdx.x >> 5;
    int h  = (blockIdx.x >> 3) & 3;
    int sl = blockIdx.x & 7;
    int v0 = sl * 64;
    int tid = threadIdx.x;
    int kb = tid & 3, vi = tid >> 2;
    int kb68 = kb * KSTR;

    float* qsp = dynsm + QS_OFF;
    float* ksp = dynsm + KS_OFF;
    float* vsp = dynsm + VS_OFF;
    float* sgp = dynsm + SG_OFF;

    const float* qp = q + (size_t)b * Tt * KDIM + h * DKk + tid;
    const float* kp = k + (size_t)b * Tt * KDIM + h * DKk + tid;
    const float* vp = v + (size_t)b * Tt * VDIM + h * DVv + v0 + tid;
    const float* gp = egp_ + (size_t)b * Tt * Hh + h;
    const float* bp = beta + (size_t)b * Tt * Hh + h;

    uint32_t qdst0 = smem_u32(qsp + kb * KSTR + vi);
    uint32_t kdst0 = smem_u32(ksp + kb * KSTR + vi);
    uint32_t vdst0 = smem_u32(vsp + (tid & 63));
    uint32_t gdst0 = smem_u32(sgp);
    const uint32_t QKROW = 4 * KSTR * 4;   // bytes per ring stage in qs/ks

    auto prefetch = [&](int t) {
        int st = t & (RD - 1);
        cpa4(qdst0 + st * QKROW, qp + (size_t)t * KDIM);
        cpa4(kdst0 + st * QKROW, kp + (size_t)t * KDIM);
        if (tid < 64)       cpa4(vdst0 + st * 256, vp + (size_t)t * VDIM);
        else if (tid == 64) cpa4(gdst0 + st * 8,     gp + (size_t)t * Hh);
        else if (tid == 65) cpa4(gdst0 + st * 8 + 4, bp + (size_t)t * Hh);
    };

    // prologue: steps 0..23 in 3 groups of 8
    #pragma unroll
    for (int i = 0; i < 3; i++) {
        #pragma unroll
        for (int j = 0; j < 8; j++) prefetch(8 * i + j);
        asm volatile("cp.async.commit_group;" ::: "memory");
    }

    u64t S2[32];
    #pragma unroll
    for (int j = 0; j < 32; j++) S2[j] = 0ull;
    u64t kreg2[32];

    float* obase = o + (size_t)b * Tt * VDIM + h * DVv + v0 + vi;

    for (int t = 0; t < Tt; t += 8) {
        // completes through step t+7; groups for t+8..t+23 in flight
        asm volatile("cp.async.wait_group %0;" :: "n"(2) : "memory");
        __syncthreads();

        // refill slots (t+24..t+31)&31 == (t-8..t-1)&31, read in the previous iteration
        if (t + 24 < Tt) {
            #pragma unroll
            for (int j = 0; j < 8; j++)
                if (t + 24 + j < Tt) prefetch(t + 24 + j);
        }
        asm volatile("cp.async.commit_group;" ::: "memory");

        #pragma unroll
        for (int u = 0; u < 8; u++) {
            int tc = t + u;
            int st = tc & (RD - 1);
            float* ksr = ksp + st * 4 * KSTR;
            float* qsr = qsp + st * 4 * KSTR;

            float eg = sgp[st * 2];
            float bt = sgp[st * 2 + 1];
            u64t eg2; PACK2(eg2, eg, eg);

            u64t p2a = 0ull, p2b = 0ull;
            #pragma unroll
            for (int jj = 0; jj < 16; jj++) {
                ulonglong2 kv = *(const ulonglong2*)&ksr[kb68 + 4 * jj];
                kreg2[2 * jj]     = kv.x;
                kreg2[2 * jj + 1] = kv.y;
                FMA2(p2a, kv.x, S2[2 * jj],     p2a);
                FMA2(p2b, kv.y, S2[2 * jj + 1], p2b);
            }
            ADD2(p2a, p2a, p2b);
            float plo, phi;
            UNPK2(plo, phi, p2a);
            float partial = plo + phi;
            partial += __shfl_xor_sync(0xffffffffu, partial, 1);
            partial += __shfl_xor_sync(0xffffffffu, partial, 2);
            float delta = (vsp[st * 64 + vi] - eg * partial) * bt;
            u64t d2; PACK2(d2, delta, delta);

            u64t o2a = 0ull, o2b = 0ull;
            #pragma unroll
            for (int jj = 0; jj < 16; jj++) {
                ulonglong2 qv = *(const ulonglong2*)&qsr[kb68 + 4 * jj];
                u64t t0, t1;
                MUL2(t0, kreg2[2 * jj],     d2);
                MUL2(t1, kreg2[2 * jj + 1], d2);
                FMA2(S2[2 * jj],     eg2, S2[2 * jj],     t0);
                FMA2(S2[2 * jj + 1], eg2, S2[2 * jj + 1], t1);
                FMA2(o2a, qv.x, S2[2 * jj],     o2a);
                FMA2(o2b, qv.y, S2[2 * jj + 1], o2b);
            }
            ADD2(o2a, o2a, o2b);
            float olo, ohi;
            UNPK2(olo, ohi, o2a);
            float opart = olo + ohi;
            opart += __shfl_xor_sync(0xffffffffu, opart, 1);
            opart += __shfl_xor_sync(0xffffffffu, opart, 2);
            if (kb == 0) obase[(size_t)tc * VDIM] = opart;
        }
    }
}

// ---------------- gated RMSNorm + silu(gate) -> half ----------------
__global__ void rmsgate_kernel(const float* __restrict__ o, const __half* __restrict__ xall,
                               const float* __restrict__ onw, __half* __restrict__ oh) {
    int rowh = blockIdx.x;
    long row = rowh >> 2;
    int h = rowh & 3;
    const float* op = o + row * VDIM + h * DVv;
    const __half* gp = xall + row * (long)NQKVG + 4096 + h * DVv;
    __half* ohp = oh + row * VDIM + h * DVv;
    float v1 = op[threadIdx.x], v2 = op[threadIdx.x + 256];
    float ss = v1 * v1 + v2 * v2;
    __shared__ float sh[8];
    int lane = threadIdx.x & 31, wid = threadIdx.x >> 5;
    #pragma unroll
    for (int off = 16; off > 0; off >>= 1) ss += __shfl_xor_sync(0xffffffffu, ss, off);
    if (lane == 0) sh[wid] = ss;
    __syncthreads();
    if (threadIdx.x == 0) {
        float a = 0.f;
        #pragma unroll
        for (int i = 0; i < 8; i++) a += sh[i];
        sh[0] = a;
    }
    __syncthreads();
    float scale = rsqrtf(sh[0] * (1.0f / DVv) + 1e-5f);
    int c1 = threadIdx.x, c2 = threadIdx.x + 256;
    ohp[c1] = __float2half(v1 * scale * onw[c1] * siluf_(__half2float(gp[c1])));
    ohp[c2] = __float2half(v2 * scale * onw[c2] * siluf_(__half2float(gp[c2])));
}

// ---------------- launcher ----------------
extern "C" void kernel_launch(void* const* d_in, const int* in_sizes, int n_in,
                              void* d_out, int out_size) {
    const float* x        = (const float*)d_in[0];
    const float* Wq       = (const float*)d_in[1];
    const float* Wk       = (const float*)d_in[2];
    const float* Wv       = (const float*)d_in[3];
    const float* Wa       = (const float*)d_in[4];
    const float* Wb       = (const float*)d_in[5];
    const float* Wg       = (const float*)d_in[6];
    const float* conv_q_w = (const float*)d_in[7];
    const float* conv_k_w = (const float*)d_in[8];
    const float* conv_v_w = (const float*)d_in[9];
    const float* A_log    = (const float*)d_in[10];
    const float* dt_bias  = (const float*)d_in[11];
    const float* o_norm_w = (const float*)d_in[12];
    const float* Wo       = (const float*)d_in[13];
    const float* ln1_w    = (const float*)d_in[14];
    const float* ln1_b    = (const float*)d_in[15];
    const float* ln2_w    = (const float*)d_in[16];
    const float* ln2_b    = (const float*)d_in[17];
    const float* ffn_w1   = (const float*)d_in[18];
    const float* ffn_b1   = (const float*)d_in[19];
    const float* ffn_w2   = (const float*)d_in[20];
    const float* ffn_b2   = (const float*)d_in[21];
    float* out = (float*)d_out;

    __half *normh, *xallh, *oh, *hbufh, *ffn1h, *wth;
    float *q, *k, *v, *gg, *bb, *o, *x2;
    cudaGetSymbolAddress((void**)&normh, g_normh);
    cudaGetSymbolAddress((void**)&xallh, g_xallh);
    cudaGetSymbolAddress((void**)&q, g_q);
    cudaGetSymbolAddress((void**)&k, g_k);
    cudaGetSymbolAddress((void**)&v, g_v);
    cudaGetSymbolAddress((void**)&gg, g_gg);
    cudaGetSymbolAddress((void**)&bb, g_bb);
    cudaGetSymbolAddress((void**)&o, g_o);
    cudaGetSymbolAddress((void**)&oh, g_oh);
    cudaGetSymbolAddress((void**)&x2, g_x2);
    cudaGetSymbolAddress((void**)&hbufh, g_hbufh);
    cudaGetSymbolAddress((void**)&ffn1h, g_ffn1h);
    cudaGetSymbolAddress((void**)&wth, g_wth);

    cudaFuncSetAttribute(hgemm<2>, cudaFuncAttributeMaxDynamicSharedMemorySize, SMEM_DYN);
    cudaFuncSetAttribute(hgemm<3>, cudaFuncAttributeMaxDynamicSharedMemorySize, SMEM_DYN);
    cudaFuncSetAttribute(hgemm<4>, cudaFuncAttributeMaxDynamicSharedMemorySize, SMEM_DYN);
    cudaFuncSetAttribute(hgemm<5>, cudaFuncAttributeMaxDynamicSharedMemorySize, SMEM_DYN);
    cudaFuncSetAttribute(scan_kernel, cudaFuncAttributeMaxDynamicSharedMemorySize, SCAN_SMEM);

    // 0: all weight transposes
    transpose_all_kernel<<<16384, dim3(32, 8)>>>(Wq, Wk, Wv, Wg, Wo, ffn_w1, ffn_w2, wth);

    // 1: LN1 -> half
    ln_kernel<<<NROWS, 256>>>(x, ln1_w, ln1_b, normh);

    // 2: g/beta (stores exp(g))
    gbeta_kernel<<<NROWS / 8, 256>>>(normh, Wa, Wb, A_log, dt_bias, gg, bb);

    // 3: fused Q|K|V|G projection -> half
    hgemm<5><<<dim3(NQKVG/128, NROWS/128), 256, SMEM_DYN>>>(normh, wth + WT_QKVG, xallh,
                                                            NROWS, NQKVG, Dd, nullptr, nullptr);

    // 4: conv + silu + l2norm for q and k
    conv_l2_kernel<<<NROWS * Hh * 2, 128>>>(xallh, conv_q_w, conv_k_w, q, k);
    // 5: conv + silu for v
    {
        long tv2 = (long)NROWS * (VDIM / 2);
        conv_silu_kernel<<<(unsigned)((tv2 + 255) / 256), 256>>>(xallh, 2048, conv_v_w, v, tv2);
    }

    // 6: scan (unroll-8, ring 32, dynamic smem)
    scan_kernel<<<Bb * Hh * 8, 256, SCAN_SMEM>>>(q, k, v, gg, bb, o);

    // 7: gated RMSNorm -> half
    rmsgate_kernel<<<NROWS * Hh, 256>>>(o, xallh, o_norm_w, oh);

    // 8: x2 = x + oh @ WoT
    hgemm<3><<<dim3(Dd/128, NROWS/128), 256, SMEM_DYN>>>(oh, wth + WT_O, x2,
                                                         NROWS, Dd, VDIM, nullptr, x);

    // 9: LN2 + FFN
    ln_kernel<<<NROWS, 256>>>(x2, ln2_w, ln2_b, hbufh);
    hgemm<2><<<dim3(FFND/128, NROWS/128), 256, SMEM_DYN>>>(hbufh, wth + WT_F1, ffn1h,
                                                           NROWS, FFND, Dd, ffn_b1, nullptr);
    hgemm<4><<<dim3(Dd/128, NROWS/128), 256, SMEM_DYN>>>(ffn1h, wth + WT_F2, out,
                                                         NROWS, Dd, FFND, ffn_b2, x2);
}